// round 4
// baseline (speedup 1.0000x reference)
#include <cuda_runtime.h>
#include <cuda_bf16.h>
#include <cstdint>
#include <cstddef>

#define NB   16
#define FIN  512
#define TD   512
#define MR   8192
#define HD   2048

#define BM   128
#define BN   128
#define STAGES 4
#define TILEB (128 * 80)                // 10240 B per matrix tile (64B data + 16B pad rows)
#define STAGEB (2 * TILEB)              // 20480 B per stage
#define SMEM_DYN (STAGES * STAGEB)      // 81920 B

// ---------------- scratch ----------------------------------------------------
__device__ __nv_bfloat16 g_xt3[(size_t)MR * 1536];
__device__ __nv_bfloat16 g_w1b[(size_t)HD * 1536];
__device__ int8_t g_w2b[(size_t)HD * HD];
__device__ int8_t g_w3b[(size_t)HD * HD];
__device__ int8_t g_w4b[(size_t)FIN * HD];
__device__ float  g_h[(size_t)MR * HD];     // L1: fp32 ; L2/3 reuse as int16
__device__ int8_t g_a[(size_t)MR * HD];
__device__ float g_mu[HD], g_rs[HD], g_ps[8 * HD], g_pq[8 * HD];

__device__ __forceinline__ float sgnf(float v) {
    return (v > 0.f) ? 1.f : ((v < 0.f) ? -1.f : 0.f);
}
__device__ __forceinline__ uint32_t smem_u32(const void* p) {
    return (uint32_t)__cvta_generic_to_shared(p);
}
__device__ __forceinline__ void cp16(uint32_t dst, const void* src) {
    asm volatile("cp.async.cg.shared.global [%0], [%1], 16;" :: "r"(dst), "l"(src));
}
__device__ __forceinline__ void ldsm4(uint32_t& r0, uint32_t& r1, uint32_t& r2, uint32_t& r3,
                                      uint32_t a) {
    asm volatile("ldmatrix.sync.aligned.m8n8.x4.shared.b16 {%0,%1,%2,%3}, [%4];"
                 : "=r"(r0), "=r"(r1), "=r"(r2), "=r"(r3) : "r"(a));
}
__device__ __forceinline__ void mma16816(float* c, const uint32_t* a, const uint32_t* b) {
    asm volatile("mma.sync.aligned.m16n8k16.row.col.f32.bf16.bf16.f32 "
                 "{%0,%1,%2,%3},{%4,%5,%6,%7},{%8,%9},{%0,%1,%2,%3};"
                 : "+f"(c[0]), "+f"(c[1]), "+f"(c[2]), "+f"(c[3])
                 : "r"(a[0]), "r"(a[1]), "r"(a[2]), "r"(a[3]), "r"(b[0]), "r"(b[1]));
}
__device__ __forceinline__ void imma16832(int* c, const uint32_t* a, const uint32_t* b) {
    asm volatile("mma.sync.aligned.m16n8k32.row.col.s32.s8.s8.s32 "
                 "{%0,%1,%2,%3},{%4,%5,%6,%7},{%8,%9},{%0,%1,%2,%3};"
                 : "+r"(c[0]), "+r"(c[1]), "+r"(c[2]), "+r"(c[3])
                 : "r"(a[0]), "r"(a[1]), "r"(a[2]), "r"(a[3]), "r"(b[0]), "r"(b[1]));
}

// ---------------- tile loader (byte-geometry: 128 rows x 64B per tile) --------
// Kb = row pitch in BYTES of the source; tile k-offset = kc*64 bytes.
__device__ __forceinline__ void load_stage(
    const char* __restrict__ A, const char* __restrict__ B,
    size_t Kb, int bm, int bn, uint32_t smbase, int tid, int stage, int kc)
{
    uint32_t sA = smbase + stage * STAGEB;
    uint32_t sB = sA + TILEB;
    const char* gA = A + (size_t)bm * Kb + (size_t)kc * 64;
    const char* gB = B + (size_t)bn * Kb + (size_t)kc * 64;
#pragma unroll
    for (int i = 0; i < 2; i++) {
        int idx = tid + i * 256;
        int r = idx >> 2, c = idx & 3;
        cp16(sA + r * 80 + c * 16, gA + (size_t)r * Kb + c * 16);
    }
#pragma unroll
    for (int i = 0; i < 2; i++) {
        int idx = tid + i * 256;
        int r = idx >> 2, c = idx & 3;
        cp16(sB + r * 80 + c * 16, gB + (size_t)r * Kb + c * 16);
    }
    asm volatile("cp.async.commit_group;" ::: "memory");
}

// ---------------- bf16 HMMA GEMM (layer 1): h fp32 = A @ B^T ------------------
__global__ void __launch_bounds__(256, 2)
gemm_bf16(const __nv_bfloat16* __restrict__ A, const __nv_bfloat16* __restrict__ B,
          float* __restrict__ C, int N, int K)
{
    extern __shared__ char smraw[];
    const uint32_t smbase = smem_u32(smraw);
    const int tid = threadIdx.x, wid = tid >> 5, lid = tid & 31;
    const int bm = blockIdx.y * BM, bn = blockIdx.x * BN;
    const int NC = K / 32;                      // BK=32 bf16 = 64B
    const int wm = (wid & 1) * 64, wn = (wid >> 1) * 32;
    const int lr = ((lid >> 3) & 1) * 8 + (lid & 7);
    const int lc = (lid >> 4) * 8;
    const size_t Kb = (size_t)K * 2;

    float acc[4][4][4];
#pragma unroll
    for (int i = 0; i < 4; i++)
#pragma unroll
        for (int j = 0; j < 4; j++)
#pragma unroll
            for (int q = 0; q < 4; q++) acc[i][j][q] = 0.f;

#pragma unroll
    for (int pc = 0; pc < STAGES - 1; ++pc)
        load_stage((const char*)A, (const char*)B, Kb, bm, bn, smbase, tid, pc, pc);

    for (int kc = 0; kc < NC; ++kc) {
        const int st = kc & (STAGES - 1);
        asm volatile("cp.async.wait_group %0;" :: "n"(STAGES - 2) : "memory");
        __syncthreads();
        const uint32_t aBase = smbase + st * STAGEB;
        const uint32_t bBase = aBase + TILEB;
#pragma unroll
        for (int ks = 0; ks < 2; ++ks) {
            uint32_t a[4][4];
#pragma unroll
            for (int i = 0; i < 4; i++)
                ldsm4(a[i][0], a[i][1], a[i][2], a[i][3],
                      aBase + (uint32_t)(wm + i * 16 + lr) * 80 + (uint32_t)(ks * 16 + lc) * 2);
            uint32_t b[4][2];
#pragma unroll
            for (int jj = 0; jj < 2; jj++) {
                uint32_t r0, r1, r2, r3;
                ldsm4(r0, r1, r2, r3,
                      bBase + (uint32_t)(wn + jj * 16 + lr) * 80 + (uint32_t)(ks * 16 + lc) * 2);
                b[jj * 2 + 0][0] = r0; b[jj * 2 + 0][1] = r2;
                b[jj * 2 + 1][0] = r1; b[jj * 2 + 1][1] = r3;
            }
#pragma unroll
            for (int i = 0; i < 4; i++)
#pragma unroll
                for (int j = 0; j < 4; j++)
                    mma16816(acc[i][j], a[i], b[j]);
        }
        int nk = kc + STAGES - 1;
        if (nk < NC)
            load_stage((const char*)A, (const char*)B, Kb, bm, bn, smbase, tid,
                       nk & (STAGES - 1), nk);
        else
            asm volatile("cp.async.commit_group;" ::: "memory");
    }

    const int row0 = lid >> 2, col0 = (lid & 3) * 2;
#pragma unroll
    for (int i = 0; i < 4; i++)
#pragma unroll
        for (int j = 0; j < 4; j++) {
            int m0 = bm + wm + i * 16 + row0;
            int n0 = bn + wn + j * 8 + col0;
            *(float2*)&C[(size_t)m0 * N + n0]       = make_float2(acc[i][j][0], acc[i][j][1]);
            *(float2*)&C[(size_t)(m0 + 8) * N + n0] = make_float2(acc[i][j][2], acc[i][j][3]);
        }
}

// ---------------- s8 IMMA GEMM (layers 2/3/4): C = A @ B^T --------------------
// EPI 0: h int16 row-major (M,N).  EPI 1: y[batch, n, t] = float(acc)*scale[n]
template <int EPI>
__global__ void __launch_bounds__(256, 2)
gemm_s8(const int8_t* __restrict__ A, const int8_t* __restrict__ B,
        void* __restrict__ Cv, int N, int K, const float* __restrict__ scale)
{
    extern __shared__ char smraw[];
    const uint32_t smbase = smem_u32(smraw);
    const int tid = threadIdx.x, wid = tid >> 5, lid = tid & 31;
    const int bm = blockIdx.y * BM, bn = blockIdx.x * BN;
    const int NC = K / 64;                      // BK=64 s8 = 64B
    const int wm = (wid & 1) * 64, wn = (wid >> 1) * 32;
    const int lr = ((lid >> 3) & 1) * 8 + (lid & 7);
    const int lc = (lid >> 4) * 8;
    const size_t Kb = (size_t)K;

    int acc[4][4][4];
#pragma unroll
    for (int i = 0; i < 4; i++)
#pragma unroll
        for (int j = 0; j < 4; j++)
#pragma unroll
            for (int q = 0; q < 4; q++) acc[i][j][q] = 0;

#pragma unroll
    for (int pc = 0; pc < STAGES - 1; ++pc)
        load_stage((const char*)A, (const char*)B, Kb, bm, bn, smbase, tid, pc, pc);

    for (int kc = 0; kc < NC; ++kc) {
        const int st = kc & (STAGES - 1);
        asm volatile("cp.async.wait_group %0;" :: "n"(STAGES - 2) : "memory");
        __syncthreads();
        const uint32_t aBase = smbase + st * STAGEB;
        const uint32_t bBase = aBase + TILEB;
#pragma unroll
        for (int ks = 0; ks < 2; ++ks) {       // two k32 chunks (32B each)
            uint32_t a[4][4];
#pragma unroll
            for (int i = 0; i < 4; i++)
                ldsm4(a[i][0], a[i][1], a[i][2], a[i][3],
                      aBase + (uint32_t)(wm + i * 16 + lr) * 80 + (uint32_t)(ks * 16 + lc) * 2);
            uint32_t b[4][2];
#pragma unroll
            for (int jj = 0; jj < 2; jj++) {
                uint32_t r0, r1, r2, r3;
                ldsm4(r0, r1, r2, r3,
                      bBase + (uint32_t)(wn + jj * 16 + lr) * 80 + (uint32_t)(ks * 16 + lc) * 2);
                b[jj * 2 + 0][0] = r0; b[jj * 2 + 0][1] = r2;
                b[jj * 2 + 1][0] = r1; b[jj * 2 + 1][1] = r3;
            }
#pragma unroll
            for (int i = 0; i < 4; i++)
#pragma unroll
                for (int j = 0; j < 4; j++)
                    imma16832(acc[i][j], a[i], b[j]);
        }
        int nk = kc + STAGES - 1;
        if (nk < NC)
            load_stage((const char*)A, (const char*)B, Kb, bm, bn, smbase, tid,
                       nk & (STAGES - 1), nk);
        else
            asm volatile("cp.async.commit_group;" ::: "memory");
    }

    const int row0 = lid >> 2, col0 = (lid & 3) * 2;
    if (EPI == 0) {
        int16_t* C = (int16_t*)Cv;
#pragma unroll
        for (int i = 0; i < 4; i++)
#pragma unroll
            for (int j = 0; j < 4; j++) {
                int m0 = bm + wm + i * 16 + row0;
                int n0 = bn + wn + j * 8 + col0;
                short2 v0 = make_short2((short)acc[i][j][0], (short)acc[i][j][1]);
                short2 v1 = make_short2((short)acc[i][j][2], (short)acc[i][j][3]);
                *(short2*)&C[(size_t)m0 * N + n0]       = v0;
                *(short2*)&C[(size_t)(m0 + 8) * N + n0] = v1;
            }
    } else {
        float* C = (float*)Cv;
#pragma unroll
        for (int i = 0; i < 4; i++) {
            int m0 = bm + wm + i * 16 + row0;
            int b0 = m0 / TD, t0 = m0 % TD;
#pragma unroll
            for (int j = 0; j < 4; j++) {
                int n0 = bn + wn + j * 8 + col0;
                float s0 = scale[n0], s1 = scale[n0 + 1];
                C[((size_t)b0 * FIN + n0) * TD + t0]         = (float)acc[i][j][0] * s0;
                C[((size_t)b0 * FIN + n0 + 1) * TD + t0]     = (float)acc[i][j][1] * s1;
                C[((size_t)b0 * FIN + n0) * TD + t0 + 8]     = (float)acc[i][j][2] * s0;
                C[((size_t)b0 * FIN + n0 + 1) * TD + t0 + 8] = (float)acc[i][j][3] * s1;
            }
        }
    }
}

// ---------------- prep kernels -------------------------------------------------
__global__ void transpose_split(const float* __restrict__ x, __nv_bfloat16* __restrict__ xt3) {
    __shared__ float tile[32][33];
    int n = blockIdx.z, t0 = blockIdx.x * 32, f0 = blockIdx.y * 32;
    const float* xp = x + (size_t)n * FIN * TD;
#pragma unroll
    for (int i = 0; i < 4; i++) {
        int f = f0 + threadIdx.y + i * 8;
        tile[threadIdx.y + i * 8][threadIdx.x] = xp[(size_t)f * TD + t0 + threadIdx.x];
    }
    __syncthreads();
#pragma unroll
    for (int i = 0; i < 4; i++) {
        int t = t0 + threadIdx.y + i * 8;
        int f = f0 + threadIdx.x;
        float v = tile[threadIdx.x][threadIdx.y + i * 8];
        __nv_bfloat16 hi = __float2bfloat16(v);
        float r1 = v - __bfloat162float(hi);
        __nv_bfloat16 md = __float2bfloat16(r1);
        float r2 = r1 - __bfloat162float(md);
        __nv_bfloat16 lo = __float2bfloat16(r2);
        size_t row = (size_t)((size_t)n * TD + t) * 1536;
        xt3[row + f] = hi;
        xt3[row + 512 + f] = md;
        xt3[row + 1024 + f] = lo;
    }
}

// vectorized s8 binarize: 4 elems/thread
__global__ void binw_s8(const float* __restrict__ W, int8_t* __restrict__ o, int n4) {
    int i = blockIdx.x * 256 + threadIdx.x;
    if (i >= n4) return;
    float4 w = *(const float4*)&W[(size_t)i * 4];
    char4 c;
    c.x = (char)(int)sgnf(w.x);
    c.y = (char)(int)sgnf(w.y);
    c.z = (char)(int)sgnf(w.z);
    c.w = (char)(int)sgnf(w.w);
    *(char4*)&o[(size_t)i * 4] = c;
}
// W1 (HD,512) -> bf16 (HD,1536), replicated 3x along K, 4 elems/thread
__global__ void binw3(const float* __restrict__ W1, __nv_bfloat16* __restrict__ o) {
    int i = blockIdx.x * 256 + threadIdx.x;           // quad index
    if (i >= HD * FIN / 4) return;
    float4 w = *(const float4*)&W1[(size_t)i * 4];
    int row = (i * 4) >> 9, k = (i * 4) & 511;
    __nv_bfloat162 p0, p1;
    p0.x = __float2bfloat16(sgnf(w.x)); p0.y = __float2bfloat16(sgnf(w.y));
    p1.x = __float2bfloat16(sgnf(w.z)); p1.y = __float2bfloat16(sgnf(w.w));
    size_t base = (size_t)row * 1536 + k;
    *(__nv_bfloat162*)&o[base]        = p0; *(__nv_bfloat162*)&o[base + 2]        = p1;
    *(__nv_bfloat162*)&o[base + 512]  = p0; *(__nv_bfloat162*)&o[base + 514]      = p1;
    *(__nv_bfloat162*)&o[base + 1024] = p0; *(__nv_bfloat162*)&o[base + 1026]     = p1;
}

// ---------------- BN stats (same accumulation order as round 3) ----------------
template <typename T>
__global__ void stats_partial(const T* __restrict__ h,
                              float* __restrict__ ps, float* __restrict__ pq) {
    int c = threadIdx.x & 31, lane = threadIdx.x >> 5;
    int col = blockIdx.x * 32 + c;
    int r0 = blockIdx.y * (MR / 8);
    float s = 0.f, sq = 0.f;
    for (int i = lane; i < MR / 8; i += 8) {
        float v = (float)h[(size_t)(r0 + i) * HD + col];
        s += v; sq += v * v;
    }
    __shared__ float ss[8][33], sv[8][33];
    ss[lane][c] = s; sv[lane][c] = sq;
    __syncthreads();
    if (lane == 0) {
        float ts = 0.f, tq = 0.f;
#pragma unroll
        for (int l = 0; l < 8; l++) { ts += ss[l][c]; tq += sv[l][c]; }
        ps[blockIdx.y * HD + col] = ts;
        pq[blockIdx.y * HD + col] = tq;
    }
}
__global__ void stats_final(const float* __restrict__ ps, const float* __restrict__ pq,
                            float* __restrict__ mu, float* __restrict__ rs) {
    int col = blockIdx.x * 256 + threadIdx.x;
    if (col >= HD) return;
    float s = 0.f, sq = 0.f;
#pragma unroll
    for (int p = 0; p < 8; p++) { s += ps[p * HD + col]; sq += pq[p * HD + col]; }
    float m = s * (1.f / MR);
    float var = sq * (1.f / MR) - m * m;
    if (var < 0.f) var = 0.f;
    mu[col] = m;
    rs[col] = rsqrtf(var + 1e-5f);
}

// ---------------- sign activation -> s8 -----------------------------------------
template <typename T>
__global__ void sign_act(const T* __restrict__ h,
                         const float* __restrict__ mu, const float* __restrict__ rs,
                         const float* __restrict__ g, const float* __restrict__ b,
                         int8_t* __restrict__ a) {
    size_t i4 = (size_t)blockIdx.x * blockDim.x + threadIdx.x;
    size_t e0 = i4 * 4;
    if (e0 >= (size_t)MR * HD) return;
    int j = (int)(e0 % HD);
    float v0 = (float)h[e0], v1 = (float)h[e0 + 1], v2 = (float)h[e0 + 2], v3 = (float)h[e0 + 3];
    char4 c;
    c.x = (char)(int)sgnf(g[j + 0] * (v0 - mu[j + 0]) * rs[j + 0] + b[j + 0]);
    c.y = (char)(int)sgnf(g[j + 1] * (v1 - mu[j + 1]) * rs[j + 1] + b[j + 1]);
    c.z = (char)(int)sgnf(g[j + 2] * (v2 - mu[j + 2]) * rs[j + 2] + b[j + 2]);
    c.w = (char)(int)sgnf(g[j + 3] * (v3 - mu[j + 3]) * rs[j + 3] + b[j + 3]);
    *(char4*)&a[e0] = c;
}

// ---------------- host orchestration --------------------------------------------
extern "C" void kernel_launch(void* const* d_in, const int* in_sizes, int n_in,
                              void* d_out, int out_size) {
    const float* x     = (const float*)d_in[0];
    const float* W1    = (const float*)d_in[2];
    const float* g1    = (const float*)d_in[3];
    const float* b1    = (const float*)d_in[4];
    const float* W2    = (const float*)d_in[5];
    const float* g2    = (const float*)d_in[6];
    const float* b2    = (const float*)d_in[7];
    const float* W3    = (const float*)d_in[8];
    const float* g3    = (const float*)d_in[9];
    const float* b3    = (const float*)d_in[10];
    const float* W4    = (const float*)d_in[11];
    const float* scale = (const float*)d_in[12];
    float* y = (float*)d_out;

    __nv_bfloat16 *xt3, *w1b;
    int8_t *w2b, *w3b, *w4b, *a;
    float *h, *mu, *rs, *ps, *pq;
    cudaGetSymbolAddress((void**)&xt3, g_xt3);
    cudaGetSymbolAddress((void**)&w1b, g_w1b);
    cudaGetSymbolAddress((void**)&w2b, g_w2b);
    cudaGetSymbolAddress((void**)&w3b, g_w3b);
    cudaGetSymbolAddress((void**)&w4b, g_w4b);
    cudaGetSymbolAddress((void**)&h,   g_h);
    cudaGetSymbolAddress((void**)&a,   g_a);
    cudaGetSymbolAddress((void**)&mu,  g_mu);
    cudaGetSymbolAddress((void**)&rs,  g_rs);
    cudaGetSymbolAddress((void**)&ps,  g_ps);
    cudaGetSymbolAddress((void**)&pq,  g_pq);
    int16_t* h16 = (int16_t*)h;

    cudaFuncSetAttribute(gemm_bf16,  cudaFuncAttributeMaxDynamicSharedMemorySize, SMEM_DYN);
    cudaFuncSetAttribute(gemm_s8<0>, cudaFuncAttributeMaxDynamicSharedMemorySize, SMEM_DYN);
    cudaFuncSetAttribute(gemm_s8<1>, cudaFuncAttributeMaxDynamicSharedMemorySize, SMEM_DYN);

    // prep
    transpose_split<<<dim3(TD / 32, FIN / 32, NB), dim3(32, 8)>>>(x, xt3);
    binw3<<<(HD * FIN / 4 + 255) / 256, 256>>>(W1, w1b);
    binw_s8<<<(HD * HD / 4 + 255) / 256, 256>>>(W2, w2b, HD * HD / 4);
    binw_s8<<<(HD * HD / 4 + 255) / 256, 256>>>(W3, w3b, HD * HD / 4);
    binw_s8<<<(FIN * HD / 4 + 255) / 256, 256>>>(W4, w4b, FIN * HD / 4);

    dim3 blk(256);
    dim3 gridStats(HD / 32, 8);
    dim3 gridSign((unsigned)(((size_t)MR * HD / 4 + 255) / 256));
    dim3 gGemm(HD / BN, MR / BM);   // (16, 64)
    dim3 gGemm4(FIN / BN, MR / BM); // (4, 64)

    // layer 1 (bf16 HMMA, K=1536): h fp32
    gemm_bf16<<<gGemm, blk, SMEM_DYN>>>(xt3, w1b, h, HD, 1536);
    stats_partial<float><<<gridStats, blk>>>(h, ps, pq);
    stats_final<<<dim3(HD / 256), blk>>>(ps, pq, mu, rs);
    sign_act<float><<<gridSign, blk>>>(h, mu, rs, g1, b1, a);

    // layer 2 (s8 IMMA): h int16
    gemm_s8<0><<<gGemm, blk, SMEM_DYN>>>(a, w2b, h16, HD, HD, nullptr);
    stats_partial<int16_t><<<gridStats, blk>>>(h16, ps, pq);
    stats_final<<<dim3(HD / 256), blk>>>(ps, pq, mu, rs);
    sign_act<int16_t><<<gridSign, blk>>>(h16, mu, rs, g2, b2, a);

    // layer 3
    gemm_s8<0><<<gGemm, blk, SMEM_DYN>>>(a, w3b, h16, HD, HD, nullptr);
    stats_partial<int16_t><<<gridStats, blk>>>(h16, ps, pq);
    stats_final<<<dim3(HD / 256), blk>>>(ps, pq, mu, rs);
    sign_act<int16_t><<<gridSign, blk>>>(h16, mu, rs, g3, b3, a);

    // layer 4 (s8 IMMA, fused scale + NFT transpose)
    gemm_s8<1><<<gGemm4, blk, SMEM_DYN>>>(a, w4b, y, FIN, HD, scale);
}

// round 5
// speedup vs baseline: 1.3989x; 1.3989x over previous
#include <cuda_runtime.h>
#include <cuda_bf16.h>
#include <cstdint>
#include <cstddef>

#define NB   16
#define FIN  512
#define TD   512
#define MR   8192
#define HD   2048

#define BM   128
#define BN   256
#define STAGES 4
#define TILEA (128 * 80)                 // 10240 B (A tile)
#define TILEBB (256 * 80)                // 20480 B (B tile)
#define STAGEB (TILEA + TILEBB)          // 30720 B per stage
#define SMEM_DYN (STAGES * STAGEB)       // 122880 B

// ---------------- scratch ----------------------------------------------------
__device__ __nv_bfloat16 g_xt3[(size_t)MR * 1536];
__device__ __nv_bfloat16 g_w1b[(size_t)HD * 1536];
__device__ __nv_bfloat16 g_w2b[(size_t)HD * HD];
__device__ __nv_bfloat16 g_w3b[(size_t)HD * HD];
__device__ __nv_bfloat16 g_w4b[(size_t)FIN * HD];
__device__ float g_h[(size_t)MR * HD];
__device__ __nv_bfloat16 g_a[(size_t)MR * HD];
__device__ float g_mu[HD], g_rs[HD], g_ps[8 * HD], g_pq[8 * HD];

__device__ __forceinline__ float sgnf(float v) {
    return (v > 0.f) ? 1.f : ((v < 0.f) ? -1.f : 0.f);
}
__device__ __forceinline__ uint32_t smem_u32(const void* p) {
    return (uint32_t)__cvta_generic_to_shared(p);
}
__device__ __forceinline__ void cp16(uint32_t dst, const void* src) {
    asm volatile("cp.async.cg.shared.global [%0], [%1], 16;" :: "r"(dst), "l"(src));
}
__device__ __forceinline__ void ldsm4(uint32_t& r0, uint32_t& r1, uint32_t& r2, uint32_t& r3,
                                      uint32_t a) {
    asm volatile("ldmatrix.sync.aligned.m8n8.x4.shared.b16 {%0,%1,%2,%3}, [%4];"
                 : "=r"(r0), "=r"(r1), "=r"(r2), "=r"(r3) : "r"(a));
}
__device__ __forceinline__ void mma16816(float* c, const uint32_t* a, const uint32_t* b) {
    asm volatile("mma.sync.aligned.m16n8k16.row.col.f32.bf16.bf16.f32 "
                 "{%0,%1,%2,%3},{%4,%5,%6,%7},{%8,%9},{%0,%1,%2,%3};"
                 : "+f"(c[0]), "+f"(c[1]), "+f"(c[2]), "+f"(c[3])
                 : "r"(a[0]), "r"(a[1]), "r"(a[2]), "r"(a[3]), "r"(b[0]), "r"(b[1]));
}

// ---------------- tile loader: A 128 rows, B 256 rows; 64B of K per stage ------
__device__ __forceinline__ void load_stage(
    const char* __restrict__ A, const char* __restrict__ B,
    size_t Kb, int bm, int bn, uint32_t smbase, int tid, int stage, int kc)
{
    uint32_t sA = smbase + stage * STAGEB;
    uint32_t sB = sA + TILEA;
    const char* gA = A + (size_t)bm * Kb + (size_t)kc * 64;
    const char* gB = B + (size_t)bn * Kb + (size_t)kc * 64;
#pragma unroll
    for (int i = 0; i < 2; i++) {
        int idx = tid + i * 256;         // 0..511
        int r = idx >> 2, c = idx & 3;
        cp16(sA + r * 80 + c * 16, gA + (size_t)r * Kb + c * 16);
    }
#pragma unroll
    for (int i = 0; i < 4; i++) {
        int idx = tid + i * 256;         // 0..1023
        int r = idx >> 2, c = idx & 3;
        cp16(sB + r * 80 + c * 16, gB + (size_t)r * Kb + c * 16);
    }
    asm volatile("cp.async.commit_group;" ::: "memory");
}

// ---------------- bf16 HMMA GEMM: C = A @ B^T ---------------------------------
// CTA 128x256, 8 warps (2M x 4N), warp tile 64x64.
// EPI 0: C fp32 row-major (M,N).  EPI 1: y[batch, n, t] = acc*scale[n], m=batch*TD+t
template <int EPI>
__global__ void __launch_bounds__(256, 1)
gemm_tc(const __nv_bfloat16* __restrict__ A, const __nv_bfloat16* __restrict__ B,
        float* __restrict__ C, int N, int K, const float* __restrict__ scale)
{
    extern __shared__ char smraw[];
    const uint32_t smbase = smem_u32(smraw);
    const int tid = threadIdx.x, wid = tid >> 5, lid = tid & 31;
    const int bm = blockIdx.y * BM, bn = blockIdx.x * BN;
    const int NC = K / 32;                       // 64B of K per stage
    const int wm = (wid & 1) * 64;               // warp M offset
    const int wn = (wid >> 1) * 64;              // warp N offset
    const int lr = ((lid >> 3) & 1) * 8 + (lid & 7);
    const int lc = (lid >> 4) * 8;
    const size_t Kb = (size_t)K * 2;

    float acc[4][8][4];
#pragma unroll
    for (int i = 0; i < 4; i++)
#pragma unroll
        for (int j = 0; j < 8; j++)
#pragma unroll
            for (int q = 0; q < 4; q++) acc[i][j][q] = 0.f;

#pragma unroll
    for (int pc = 0; pc < STAGES - 1; ++pc)
        load_stage((const char*)A, (const char*)B, Kb, bm, bn, smbase, tid, pc, pc);

    for (int kc = 0; kc < NC; ++kc) {
        const int st = kc & (STAGES - 1);
        asm volatile("cp.async.wait_group %0;" :: "n"(STAGES - 2) : "memory");
        __syncthreads();
        const uint32_t aBase = smbase + st * STAGEB;
        const uint32_t bBase = aBase + TILEA;
#pragma unroll
        for (int ks = 0; ks < 2; ++ks) {
            uint32_t a[4][4];
#pragma unroll
            for (int i = 0; i < 4; i++)
                ldsm4(a[i][0], a[i][1], a[i][2], a[i][3],
                      aBase + (uint32_t)(wm + i * 16 + lr) * 80 + (uint32_t)(ks * 16 + lc) * 2);
            uint32_t b[8][2];
#pragma unroll
            for (int jj = 0; jj < 4; jj++) {
                uint32_t r0, r1, r2, r3;
                ldsm4(r0, r1, r2, r3,
                      bBase + (uint32_t)(wn + jj * 16 + lr) * 80 + (uint32_t)(ks * 16 + lc) * 2);
                b[jj * 2 + 0][0] = r0; b[jj * 2 + 0][1] = r2;
                b[jj * 2 + 1][0] = r1; b[jj * 2 + 1][1] = r3;
            }
#pragma unroll
            for (int i = 0; i < 4; i++)
#pragma unroll
                for (int j = 0; j < 8; j++)
                    mma16816(acc[i][j], a[i], b[j]);
        }
        int nk = kc + STAGES - 1;
        if (nk < NC)
            load_stage((const char*)A, (const char*)B, Kb, bm, bn, smbase, tid,
                       nk & (STAGES - 1), nk);
        else
            asm volatile("cp.async.commit_group;" ::: "memory");
    }

    const int row0 = lid >> 2, col0 = (lid & 3) * 2;
    if (EPI == 0) {
#pragma unroll
        for (int i = 0; i < 4; i++)
#pragma unroll
            for (int j = 0; j < 8; j++) {
                int m0 = bm + wm + i * 16 + row0;
                int n0 = bn + wn + j * 8 + col0;
                *(float2*)&C[(size_t)m0 * N + n0]       = make_float2(acc[i][j][0], acc[i][j][1]);
                *(float2*)&C[(size_t)(m0 + 8) * N + n0] = make_float2(acc[i][j][2], acc[i][j][3]);
            }
    } else {
#pragma unroll
        for (int i = 0; i < 4; i++) {
            int m0 = bm + wm + i * 16 + row0;
            int b0 = m0 / TD, t0 = m0 % TD;
#pragma unroll
            for (int j = 0; j < 8; j++) {
                int n0 = bn + wn + j * 8 + col0;
                float s0 = scale[n0], s1 = scale[n0 + 1];
                C[((size_t)b0 * FIN + n0) * TD + t0]         = acc[i][j][0] * s0;
                C[((size_t)b0 * FIN + n0 + 1) * TD + t0]     = acc[i][j][1] * s1;
                C[((size_t)b0 * FIN + n0) * TD + t0 + 8]     = acc[i][j][2] * s0;
                C[((size_t)b0 * FIN + n0 + 1) * TD + t0 + 8] = acc[i][j][3] * s1;
            }
        }
    }
}

// ---------------- prep kernels -------------------------------------------------
__global__ void transpose_split(const float* __restrict__ x, __nv_bfloat16* __restrict__ xt3) {
    __shared__ float tile[32][33];
    int n = blockIdx.z, t0 = blockIdx.x * 32, f0 = blockIdx.y * 32;
    const float* xp = x + (size_t)n * FIN * TD;
#pragma unroll
    for (int i = 0; i < 4; i++) {
        int f = f0 + threadIdx.y + i * 8;
        tile[threadIdx.y + i * 8][threadIdx.x] = xp[(size_t)f * TD + t0 + threadIdx.x];
    }
    __syncthreads();
#pragma unroll
    for (int i = 0; i < 4; i++) {
        int t = t0 + threadIdx.y + i * 8;
        int f = f0 + threadIdx.x;
        float v = tile[threadIdx.x][threadIdx.y + i * 8];
        __nv_bfloat16 hi = __float2bfloat16(v);
        float r1 = v - __bfloat162float(hi);
        __nv_bfloat16 md = __float2bfloat16(r1);
        float r2 = r1 - __bfloat162float(md);
        __nv_bfloat16 lo = __float2bfloat16(r2);
        size_t row = (size_t)((size_t)n * TD + t) * 1536;
        xt3[row + f] = hi;
        xt3[row + 512 + f] = md;
        xt3[row + 1024 + f] = lo;
    }
}

// vectorized bf16 binarize: 4 elems/thread
__global__ void binw_bf16(const float* __restrict__ W, __nv_bfloat16* __restrict__ o, int n4) {
    int i = blockIdx.x * 256 + threadIdx.x;
    if (i >= n4) return;
    float4 w = *(const float4*)&W[(size_t)i * 4];
    __nv_bfloat162 p0, p1;
    p0.x = __float2bfloat16(sgnf(w.x)); p0.y = __float2bfloat16(sgnf(w.y));
    p1.x = __float2bfloat16(sgnf(w.z)); p1.y = __float2bfloat16(sgnf(w.w));
    *(__nv_bfloat162*)&o[(size_t)i * 4]     = p0;
    *(__nv_bfloat162*)&o[(size_t)i * 4 + 2] = p1;
}
// W1 (HD,512) -> bf16 (HD,1536), replicated 3x along K, 4 elems/thread
__global__ void binw3(const float* __restrict__ W1, __nv_bfloat16* __restrict__ o) {
    int i = blockIdx.x * 256 + threadIdx.x;
    if (i >= HD * FIN / 4) return;
    float4 w = *(const float4*)&W1[(size_t)i * 4];
    int row = (i * 4) >> 9, k = (i * 4) & 511;
    __nv_bfloat162 p0, p1;
    p0.x = __float2bfloat16(sgnf(w.x)); p0.y = __float2bfloat16(sgnf(w.y));
    p1.x = __float2bfloat16(sgnf(w.z)); p1.y = __float2bfloat16(sgnf(w.w));
    size_t base = (size_t)row * 1536 + k;
    *(__nv_bfloat162*)&o[base]        = p0; *(__nv_bfloat162*)&o[base + 2]    = p1;
    *(__nv_bfloat162*)&o[base + 512]  = p0; *(__nv_bfloat162*)&o[base + 514]  = p1;
    *(__nv_bfloat162*)&o[base + 1024] = p0; *(__nv_bfloat162*)&o[base + 1026] = p1;
}

// ---------------- BN stats (identical to round 3: bit-identical mu/rs) ---------
__global__ void stats_partial(const float* __restrict__ h,
                              float* __restrict__ ps, float* __restrict__ pq) {
    int c = threadIdx.x & 31, lane = threadIdx.x >> 5;
    int col = blockIdx.x * 32 + c;
    int r0 = blockIdx.y * (MR / 8);
    float s = 0.f, sq = 0.f;
    for (int i = lane; i < MR / 8; i += 8) {
        float v = h[(size_t)(r0 + i) * HD + col];
        s += v; sq += v * v;
    }
    __shared__ float ss[8][33], sv[8][33];
    ss[lane][c] = s; sv[lane][c] = sq;
    __syncthreads();
    if (lane == 0) {
        float ts = 0.f, tq = 0.f;
#pragma unroll
        for (int l = 0; l < 8; l++) { ts += ss[l][c]; tq += sv[l][c]; }
        ps[blockIdx.y * HD + col] = ts;
        pq[blockIdx.y * HD + col] = tq;
    }
}
__global__ void stats_final(const float* __restrict__ ps, const float* __restrict__ pq,
                            float* __restrict__ mu, float* __restrict__ rs) {
    int col = blockIdx.x * 256 + threadIdx.x;
    if (col >= HD) return;
    float s = 0.f, sq = 0.f;
#pragma unroll
    for (int p = 0; p < 8; p++) { s += ps[p * HD + col]; sq += pq[p * HD + col]; }
    float m = s * (1.f / MR);
    float var = sq * (1.f / MR) - m * m;
    if (var < 0.f) var = 0.f;
    mu[col] = m;
    rs[col] = rsqrtf(var + 1e-5f);
}

// ---------------- sign activation -> bf16 ---------------------------------------
__global__ void sign_act(const float* __restrict__ h,
                         const float* __restrict__ mu, const float* __restrict__ rs,
                         const float* __restrict__ g, const float* __restrict__ b,
                         __nv_bfloat16* __restrict__ a) {
    size_t i4 = (size_t)blockIdx.x * blockDim.x + threadIdx.x;
    size_t e0 = i4 * 4;
    if (e0 >= (size_t)MR * HD) return;
    int j = (int)(e0 % HD);
    float4 hv = *(const float4*)&h[e0];
    float s0 = sgnf(g[j + 0] * (hv.x - mu[j + 0]) * rs[j + 0] + b[j + 0]);
    float s1 = sgnf(g[j + 1] * (hv.y - mu[j + 1]) * rs[j + 1] + b[j + 1]);
    float s2 = sgnf(g[j + 2] * (hv.z - mu[j + 2]) * rs[j + 2] + b[j + 2]);
    float s3 = sgnf(g[j + 3] * (hv.w - mu[j + 3]) * rs[j + 3] + b[j + 3]);
    __nv_bfloat162 p0, p1;
    p0.x = __float2bfloat16(s0); p0.y = __float2bfloat16(s1);
    p1.x = __float2bfloat16(s2); p1.y = __float2bfloat16(s3);
    *(__nv_bfloat162*)&a[e0] = p0;
    *(__nv_bfloat162*)&a[e0 + 2] = p1;
}

// ---------------- host orchestration --------------------------------------------
extern "C" void kernel_launch(void* const* d_in, const int* in_sizes, int n_in,
                              void* d_out, int out_size) {
    const float* x     = (const float*)d_in[0];
    const float* W1    = (const float*)d_in[2];
    const float* g1    = (const float*)d_in[3];
    const float* b1    = (const float*)d_in[4];
    const float* W2    = (const float*)d_in[5];
    const float* g2    = (const float*)d_in[6];
    const float* b2    = (const float*)d_in[7];
    const float* W3    = (const float*)d_in[8];
    const float* g3    = (const float*)d_in[9];
    const float* b3    = (const float*)d_in[10];
    const float* W4    = (const float*)d_in[11];
    const float* scale = (const float*)d_in[12];
    float* y = (float*)d_out;

    __nv_bfloat16 *xt3, *w1b, *w2b, *w3b, *w4b, *a;
    float *h, *mu, *rs, *ps, *pq;
    cudaGetSymbolAddress((void**)&xt3, g_xt3);
    cudaGetSymbolAddress((void**)&w1b, g_w1b);
    cudaGetSymbolAddress((void**)&w2b, g_w2b);
    cudaGetSymbolAddress((void**)&w3b, g_w3b);
    cudaGetSymbolAddress((void**)&w4b, g_w4b);
    cudaGetSymbolAddress((void**)&h,   g_h);
    cudaGetSymbolAddress((void**)&a,   g_a);
    cudaGetSymbolAddress((void**)&mu,  g_mu);
    cudaGetSymbolAddress((void**)&rs,  g_rs);
    cudaGetSymbolAddress((void**)&ps,  g_ps);
    cudaGetSymbolAddress((void**)&pq,  g_pq);

    cudaFuncSetAttribute(gemm_tc<0>, cudaFuncAttributeMaxDynamicSharedMemorySize, SMEM_DYN);
    cudaFuncSetAttribute(gemm_tc<1>, cudaFuncAttributeMaxDynamicSharedMemorySize, SMEM_DYN);

    // prep
    transpose_split<<<dim3(TD / 32, FIN / 32, NB), dim3(32, 8)>>>(x, xt3);
    binw3<<<(HD * FIN / 4 + 255) / 256, 256>>>(W1, w1b);
    binw_bf16<<<(HD * HD / 4 + 255) / 256, 256>>>(W2, w2b, HD * HD / 4);
    binw_bf16<<<(HD * HD / 4 + 255) / 256, 256>>>(W3, w3b, HD * HD / 4);
    binw_bf16<<<(FIN * HD / 4 + 255) / 256, 256>>>(W4, w4b, FIN * HD / 4);

    dim3 blk(256);
    dim3 gridStats(HD / 32, 8);
    dim3 gridSign((unsigned)(((size_t)MR * HD / 4 + 255) / 256));
    dim3 gGemm(HD / BN, MR / BM);   // (8, 64)
    dim3 gGemm4(FIN / BN, MR / BM); // (2, 64)

    // layer 1 (K=1536 triple-split)
    gemm_tc<0><<<gGemm, blk, SMEM_DYN>>>(xt3, w1b, h, HD, 1536, nullptr);
    stats_partial<<<gridStats, blk>>>(h, ps, pq);
    stats_final<<<dim3(HD / 256), blk>>>(ps, pq, mu, rs);
    sign_act<<<gridSign, blk>>>(h, mu, rs, g1, b1, a);

    // layer 2
    gemm_tc<0><<<gGemm, blk, SMEM_DYN>>>(a, w2b, h, HD, HD, nullptr);
    stats_partial<<<gridStats, blk>>>(h, ps, pq);
    stats_final<<<dim3(HD / 256), blk>>>(ps, pq, mu, rs);
    sign_act<<<gridSign, blk>>>(h, mu, rs, g2, b2, a);

    // layer 3
    gemm_tc<0><<<gGemm, blk, SMEM_DYN>>>(a, w3b, h, HD, HD, nullptr);
    stats_partial<<<gridStats, blk>>>(h, ps, pq);
    stats_final<<<dim3(HD / 256), blk>>>(ps, pq, mu, rs);
    sign_act<<<gridSign, blk>>>(h, mu, rs, g3, b3, a);

    // layer 4 (fused scale + NFT transpose)
    gemm_tc<1><<<gGemm4, blk, SMEM_DYN>>>(a, w4b, y, FIN, HD, scale);
}

// round 6
// speedup vs baseline: 1.6637x; 1.1892x over previous
#include <cuda_runtime.h>
#include <cuda_bf16.h>
#include <cuda_fp16.h>
#include <cstdint>
#include <cstddef>

#define NB   16
#define FIN  512
#define TD   512
#define MR   8192
#define HD   2048

#define BM   128
#define BN   128
#define STAGES 4
#define TILEB (128 * 80)                // 10240 B per matrix tile (64B data + 16B pad)
#define STAGEB (2 * TILEB)              // 20480 B
#define SMEM_DYN (STAGES * STAGEB)      // 81920 B

// ---------------- scratch ----------------------------------------------------
__device__ __nv_bfloat16 g_xt3[(size_t)MR * 1536];
__device__ __nv_bfloat16 g_w1b[(size_t)HD * 1536];
__device__ __half g_w2b[(size_t)HD * HD];
__device__ __half g_w3b[(size_t)HD * HD];
__device__ __half g_w4b[(size_t)FIN * HD];
__device__ float  g_h[(size_t)MR * HD];   // layer1 fp32; layers 2/3 reuse as fp16
__device__ __half g_a[(size_t)MR * HD];
__device__ float g_mu[HD], g_rs[HD], g_ps[8 * HD], g_pq[8 * HD];

__device__ __forceinline__ float sgnf(float v) {
    return (v > 0.f) ? 1.f : ((v < 0.f) ? -1.f : 0.f);
}
__device__ __forceinline__ uint32_t smem_u32(const void* p) {
    return (uint32_t)__cvta_generic_to_shared(p);
}
__device__ __forceinline__ void cp16(uint32_t dst, const void* src) {
    asm volatile("cp.async.cg.shared.global [%0], [%1], 16;" :: "r"(dst), "l"(src));
}
__device__ __forceinline__ void ldsm4(uint32_t& r0, uint32_t& r1, uint32_t& r2, uint32_t& r3,
                                      uint32_t a) {
    asm volatile("ldmatrix.sync.aligned.m8n8.x4.shared.b16 {%0,%1,%2,%3}, [%4];"
                 : "=r"(r0), "=r"(r1), "=r"(r2), "=r"(r3) : "r"(a));
}
__device__ __forceinline__ void mma_bf16_f32(float* c, const uint32_t* a, const uint32_t* b) {
    asm volatile("mma.sync.aligned.m16n8k16.row.col.f32.bf16.bf16.f32 "
                 "{%0,%1,%2,%3},{%4,%5,%6,%7},{%8,%9},{%0,%1,%2,%3};"
                 : "+f"(c[0]), "+f"(c[1]), "+f"(c[2]), "+f"(c[3])
                 : "r"(a[0]), "r"(a[1]), "r"(a[2]), "r"(a[3]), "r"(b[0]), "r"(b[1]));
}
__device__ __forceinline__ void mma_f16_f16(uint32_t* c, const uint32_t* a, const uint32_t* b) {
    asm volatile("mma.sync.aligned.m16n8k16.row.col.f16.f16.f16.f16 "
                 "{%0,%1},{%2,%3,%4,%5},{%6,%7},{%0,%1};"
                 : "+r"(c[0]), "+r"(c[1])
                 : "r"(a[0]), "r"(a[1]), "r"(a[2]), "r"(a[3]), "r"(b[0]), "r"(b[1]));
}

// ---------------- tile loader (byte-geometry: 128 rows x 64B) ------------------
__device__ __forceinline__ void load_stage(
    const char* __restrict__ A, const char* __restrict__ B,
    size_t Kb, int bm, int bn, uint32_t smbase, int tid, int stage, int kc)
{
    uint32_t sA = smbase + stage * STAGEB;
    uint32_t sB = sA + TILEB;
    const char* gA = A + (size_t)bm * Kb + (size_t)kc * 64;
    const char* gB = B + (size_t)bn * Kb + (size_t)kc * 64;
#pragma unroll
    for (int i = 0; i < 2; i++) {
        int idx = tid + i * 256;
        int r = idx >> 2, c = idx & 3;
        cp16(sA + r * 80 + c * 16, gA + (size_t)r * Kb + c * 16);
    }
#pragma unroll
    for (int i = 0; i < 2; i++) {
        int idx = tid + i * 256;
        int r = idx >> 2, c = idx & 3;
        cp16(sB + r * 80 + c * 16, gB + (size_t)r * Kb + c * 16);
    }
    asm volatile("cp.async.commit_group;" ::: "memory");
}

// ---------------- bf16/f32 GEMM (layer 1) --------------------------------------
__global__ void __launch_bounds__(256, 2)
gemm_bf16(const __nv_bfloat16* __restrict__ A, const __nv_bfloat16* __restrict__ B,
          float* __restrict__ C, int N, int K)
{
    extern __shared__ char smraw[];
    const uint32_t smbase = smem_u32(smraw);
    const int tid = threadIdx.x, wid = tid >> 5, lid = tid & 31;
    const int bm = blockIdx.y * BM, bn = blockIdx.x * BN;
    const int NC = K / 32;
    const int wm = (wid & 1) * 64, wn = (wid >> 1) * 32;
    const int lr = ((lid >> 3) & 1) * 8 + (lid & 7);
    const int lc = (lid >> 4) * 8;
    const size_t Kb = (size_t)K * 2;

    float acc[4][4][4];
#pragma unroll
    for (int i = 0; i < 4; i++)
#pragma unroll
        for (int j = 0; j < 4; j++)
#pragma unroll
            for (int q = 0; q < 4; q++) acc[i][j][q] = 0.f;

#pragma unroll
    for (int pc = 0; pc < STAGES - 1; ++pc)
        load_stage((const char*)A, (const char*)B, Kb, bm, bn, smbase, tid, pc, pc);

    for (int kc = 0; kc < NC; ++kc) {
        const int st = kc & (STAGES - 1);
        asm volatile("cp.async.wait_group %0;" :: "n"(STAGES - 2) : "memory");
        __syncthreads();
        const uint32_t aBase = smbase + st * STAGEB;
        const uint32_t bBase = aBase + TILEB;
#pragma unroll
        for (int ks = 0; ks < 2; ++ks) {
            uint32_t a[4][4];
#pragma unroll
            for (int i = 0; i < 4; i++)
                ldsm4(a[i][0], a[i][1], a[i][2], a[i][3],
                      aBase + (uint32_t)(wm + i * 16 + lr) * 80 + (uint32_t)(ks * 16 + lc) * 2);
            uint32_t b[4][2];
#pragma unroll
            for (int jj = 0; jj < 2; jj++) {
                uint32_t r0, r1, r2, r3;
                ldsm4(r0, r1, r2, r3,
                      bBase + (uint32_t)(wn + jj * 16 + lr) * 80 + (uint32_t)(ks * 16 + lc) * 2);
                b[jj * 2 + 0][0] = r0; b[jj * 2 + 0][1] = r2;
                b[jj * 2 + 1][0] = r1; b[jj * 2 + 1][1] = r3;
            }
#pragma unroll
            for (int i = 0; i < 4; i++)
#pragma unroll
                for (int j = 0; j < 4; j++)
                    mma_bf16_f32(acc[i][j], a[i], b[j]);
        }
        int nk = kc + STAGES - 1;
        if (nk < NC)
            load_stage((const char*)A, (const char*)B, Kb, bm, bn, smbase, tid,
                       nk & (STAGES - 1), nk);
        else
            asm volatile("cp.async.commit_group;" ::: "memory");
    }

    const int row0 = lid >> 2, col0 = (lid & 3) * 2;
#pragma unroll
    for (int i = 0; i < 4; i++)
#pragma unroll
        for (int j = 0; j < 4; j++) {
            int m0 = bm + wm + i * 16 + row0;
            int n0 = bn + wn + j * 8 + col0;
            *(float2*)&C[(size_t)m0 * N + n0]       = make_float2(acc[i][j][0], acc[i][j][1]);
            *(float2*)&C[(size_t)(m0 + 8) * N + n0] = make_float2(acc[i][j][2], acc[i][j][3]);
        }
}

// ---------------- f16/f16 GEMM (layers 2/3/4): exact integer math --------------
// EPI 0: h fp16 row-major (M,N).  EPI 1: y[batch, n, t] = float(acc)*scale[n]
template <int EPI>
__global__ void __launch_bounds__(256, 2)
gemm_f16(const __half* __restrict__ A, const __half* __restrict__ B,
         void* __restrict__ Cv, int N, int K, const float* __restrict__ scale)
{
    extern __shared__ char smraw[];
    const uint32_t smbase = smem_u32(smraw);
    const int tid = threadIdx.x, wid = tid >> 5, lid = tid & 31;
    const int bm = blockIdx.y * BM, bn = blockIdx.x * BN;
    const int NC = K / 32;
    const int wm = (wid & 1) * 64, wn = (wid >> 1) * 32;
    const int lr = ((lid >> 3) & 1) * 8 + (lid & 7);
    const int lc = (lid >> 4) * 8;
    const size_t Kb = (size_t)K * 2;

    uint32_t acc[4][4][2];
#pragma unroll
    for (int i = 0; i < 4; i++)
#pragma unroll
        for (int j = 0; j < 4; j++) { acc[i][j][0] = 0u; acc[i][j][1] = 0u; }

#pragma unroll
    for (int pc = 0; pc < STAGES - 1; ++pc)
        load_stage((const char*)A, (const char*)B, Kb, bm, bn, smbase, tid, pc, pc);

    for (int kc = 0; kc < NC; ++kc) {
        const int st = kc & (STAGES - 1);
        asm volatile("cp.async.wait_group %0;" :: "n"(STAGES - 2) : "memory");
        __syncthreads();
        const uint32_t aBase = smbase + st * STAGEB;
        const uint32_t bBase = aBase + TILEB;
#pragma unroll
        for (int ks = 0; ks < 2; ++ks) {
            uint32_t a[4][4];
#pragma unroll
            for (int i = 0; i < 4; i++)
                ldsm4(a[i][0], a[i][1], a[i][2], a[i][3],
                      aBase + (uint32_t)(wm + i * 16 + lr) * 80 + (uint32_t)(ks * 16 + lc) * 2);
            uint32_t b[4][2];
#pragma unroll
            for (int jj = 0; jj < 2; jj++) {
                uint32_t r0, r1, r2, r3;
                ldsm4(r0, r1, r2, r3,
                      bBase + (uint32_t)(wn + jj * 16 + lr) * 80 + (uint32_t)(ks * 16 + lc) * 2);
                b[jj * 2 + 0][0] = r0; b[jj * 2 + 0][1] = r2;
                b[jj * 2 + 1][0] = r1; b[jj * 2 + 1][1] = r3;
            }
#pragma unroll
            for (int i = 0; i < 4; i++)
#pragma unroll
                for (int j = 0; j < 4; j++)
                    mma_f16_f16(acc[i][j], a[i], b[j]);
        }
        int nk = kc + STAGES - 1;
        if (nk < NC)
            load_stage((const char*)A, (const char*)B, Kb, bm, bn, smbase, tid,
                       nk & (STAGES - 1), nk);
        else
            asm volatile("cp.async.commit_group;" ::: "memory");
    }

    const int row0 = lid >> 2, col0 = (lid & 3) * 2;
    if (EPI == 0) {
        __half* C = (__half*)Cv;
#pragma unroll
        for (int i = 0; i < 4; i++)
#pragma unroll
            for (int j = 0; j < 4; j++) {
                int m0 = bm + wm + i * 16 + row0;
                int n0 = bn + wn + j * 8 + col0;
                *(uint32_t*)&C[(size_t)m0 * N + n0]       = acc[i][j][0];
                *(uint32_t*)&C[(size_t)(m0 + 8) * N + n0] = acc[i][j][1];
            }
    } else {
        float* C = (float*)Cv;
#pragma unroll
        for (int i = 0; i < 4; i++) {
            int m0 = bm + wm + i * 16 + row0;
            int b0 = m0 / TD, t0 = m0 % TD;
#pragma unroll
            for (int j = 0; j < 4; j++) {
                int n0 = bn + wn + j * 8 + col0;
                float s0 = scale[n0], s1 = scale[n0 + 1];
                __half2 v0 = *(__half2*)&acc[i][j][0];
                __half2 v1 = *(__half2*)&acc[i][j][1];
                C[((size_t)b0 * FIN + n0) * TD + t0]         = __low2float(v0) * s0;
                C[((size_t)b0 * FIN + n0 + 1) * TD + t0]     = __high2float(v0) * s1;
                C[((size_t)b0 * FIN + n0) * TD + t0 + 8]     = __low2float(v1) * s0;
                C[((size_t)b0 * FIN + n0 + 1) * TD + t0 + 8] = __high2float(v1) * s1;
            }
        }
    }
}

// ---------------- prep kernels -------------------------------------------------
__global__ void transpose_split(const float* __restrict__ x, __nv_bfloat16* __restrict__ xt3) {
    __shared__ float tile[32][33];
    int n = blockIdx.z, t0 = blockIdx.x * 32, f0 = blockIdx.y * 32;
    const float* xp = x + (size_t)n * FIN * TD;
#pragma unroll
    for (int i = 0; i < 4; i++) {
        int f = f0 + threadIdx.y + i * 8;
        tile[threadIdx.y + i * 8][threadIdx.x] = xp[(size_t)f * TD + t0 + threadIdx.x];
    }
    __syncthreads();
#pragma unroll
    for (int i = 0; i < 4; i++) {
        int t = t0 + threadIdx.y + i * 8;
        int f = f0 + threadIdx.x;
        float v = tile[threadIdx.x][threadIdx.y + i * 8];
        __nv_bfloat16 hi = __float2bfloat16(v);
        float r1 = v - __bfloat162float(hi);
        __nv_bfloat16 md = __float2bfloat16(r1);
        float r2 = r1 - __bfloat162float(md);
        __nv_bfloat16 lo = __float2bfloat16(r2);
        size_t row = (size_t)((size_t)n * TD + t) * 1536;
        xt3[row + f] = hi;
        xt3[row + 512 + f] = md;
        xt3[row + 1024 + f] = lo;
    }
}

// fp16 binarize, 4 elems/thread
__global__ void binw_f16(const float* __restrict__ W, __half* __restrict__ o, int n4) {
    int i = blockIdx.x * 256 + threadIdx.x;
    if (i >= n4) return;
    float4 w = *(const float4*)&W[(size_t)i * 4];
    __half2 p0 = __floats2half2_rn(sgnf(w.x), sgnf(w.y));
    __half2 p1 = __floats2half2_rn(sgnf(w.z), sgnf(w.w));
    *(__half2*)&o[(size_t)i * 4]     = p0;
    *(__half2*)&o[(size_t)i * 4 + 2] = p1;
}
// W1 (HD,512) -> bf16 (HD,1536), replicated 3x along K
__global__ void binw3(const float* __restrict__ W1, __nv_bfloat16* __restrict__ o) {
    int i = blockIdx.x * 256 + threadIdx.x;
    if (i >= HD * FIN / 4) return;
    float4 w = *(const float4*)&W1[(size_t)i * 4];
    int row = (i * 4) >> 9, k = (i * 4) & 511;
    __nv_bfloat162 p0, p1;
    p0.x = __float2bfloat16(sgnf(w.x)); p0.y = __float2bfloat16(sgnf(w.y));
    p1.x = __float2bfloat16(sgnf(w.z)); p1.y = __float2bfloat16(sgnf(w.w));
    size_t base = (size_t)row * 1536 + k;
    *(__nv_bfloat162*)&o[base]        = p0; *(__nv_bfloat162*)&o[base + 2]    = p1;
    *(__nv_bfloat162*)&o[base + 512]  = p0; *(__nv_bfloat162*)&o[base + 514]  = p1;
    *(__nv_bfloat162*)&o[base + 1024] = p0; *(__nv_bfloat162*)&o[base + 1026] = p1;
}

// ---------------- BN stats (fp32-h variant: layer 1) ---------------------------
__global__ void stats_partial_f32(const float* __restrict__ h,
                                  float* __restrict__ ps, float* __restrict__ pq) {
    int c = threadIdx.x & 31, lane = threadIdx.x >> 5;
    int col = blockIdx.x * 32 + c;
    int r0 = blockIdx.y * (MR / 8);
    float s = 0.f, sq = 0.f;
    for (int i = lane; i < MR / 8; i += 8) {
        float v = h[(size_t)(r0 + i) * HD + col];
        s += v; sq += v * v;
    }
    __shared__ float ss[8][33], sv[8][33];
    ss[lane][c] = s; sv[lane][c] = sq;
    __syncthreads();
    if (lane == 0) {
        float ts = 0.f, tq = 0.f;
#pragma unroll
        for (int l = 0; l < 8; l++) { ts += ss[l][c]; tq += sv[l][c]; }
        ps[blockIdx.y * HD + col] = ts;
        pq[blockIdx.y * HD + col] = tq;
    }
}
// fp16-h variant (layers 2/3): identical summation values (h is exact integer)
__global__ void stats_partial_f16(const __half* __restrict__ h,
                                  float* __restrict__ ps, float* __restrict__ pq) {
    int c = threadIdx.x & 31, lane = threadIdx.x >> 5;
    int col = blockIdx.x * 32 + c;
    int r0 = blockIdx.y * (MR / 8);
    float s = 0.f, sq = 0.f;
    for (int i = lane; i < MR / 8; i += 8) {
        float v = __half2float(h[(size_t)(r0 + i) * HD + col]);
        s += v; sq += v * v;
    }
    __shared__ float ss[8][33], sv[8][33];
    ss[lane][c] = s; sv[lane][c] = sq;
    __syncthreads();
    if (lane == 0) {
        float ts = 0.f, tq = 0.f;
#pragma unroll
        for (int l = 0; l < 8; l++) { ts += ss[l][c]; tq += sv[l][c]; }
        ps[blockIdx.y * HD + col] = ts;
        pq[blockIdx.y * HD + col] = tq;
    }
}
__global__ void stats_final(const float* __restrict__ ps, const float* __restrict__ pq,
                            float* __restrict__ mu, float* __restrict__ rs) {
    int col = blockIdx.x * 256 + threadIdx.x;
    if (col >= HD) return;
    float s = 0.f, sq = 0.f;
#pragma unroll
    for (int p = 0; p < 8; p++) { s += ps[p * HD + col]; sq += pq[p * HD + col]; }
    float m = s * (1.f / MR);
    float var = sq * (1.f / MR) - m * m;
    if (var < 0.f) var = 0.f;
    mu[col] = m;
    rs[col] = rsqrtf(var + 1e-5f);
}

// ---------------- sign activation -> fp16 ---------------------------------------
__global__ void sign_act_f32(const float* __restrict__ h,
                             const float* __restrict__ mu, const float* __restrict__ rs,
                             const float* __restrict__ g, const float* __restrict__ b,
                             __half* __restrict__ a) {
    size_t i4 = (size_t)blockIdx.x * blockDim.x + threadIdx.x;
    size_t e0 = i4 * 4;
    if (e0 >= (size_t)MR * HD) return;
    int j = (int)(e0 % HD);
    float4 hv = *(const float4*)&h[e0];
    float s0 = sgnf(g[j + 0] * (hv.x - mu[j + 0]) * rs[j + 0] + b[j + 0]);
    float s1 = sgnf(g[j + 1] * (hv.y - mu[j + 1]) * rs[j + 1] + b[j + 1]);
    float s2 = sgnf(g[j + 2] * (hv.z - mu[j + 2]) * rs[j + 2] + b[j + 2]);
    float s3 = sgnf(g[j + 3] * (hv.w - mu[j + 3]) * rs[j + 3] + b[j + 3]);
    *(__half2*)&a[e0]     = __floats2half2_rn(s0, s1);
    *(__half2*)&a[e0 + 2] = __floats2half2_rn(s2, s3);
}
__global__ void sign_act_f16(const __half* __restrict__ h,
                             const float* __restrict__ mu, const float* __restrict__ rs,
                             const float* __restrict__ g, const float* __restrict__ b,
                             __half* __restrict__ a) {
    size_t i4 = (size_t)blockIdx.x * blockDim.x + threadIdx.x;
    size_t e0 = i4 * 4;
    if (e0 >= (size_t)MR * HD) return;
    int j = (int)(e0 % HD);
    __half2 h0 = *(const __half2*)&h[e0];
    __half2 h1 = *(const __half2*)&h[e0 + 2];
    float v0 = __low2float(h0), v1 = __high2float(h0);
    float v2 = __low2float(h1), v3 = __high2float(h1);
    float s0 = sgnf(g[j + 0] * (v0 - mu[j + 0]) * rs[j + 0] + b[j + 0]);
    float s1 = sgnf(g[j + 1] * (v1 - mu[j + 1]) * rs[j + 1] + b[j + 1]);
    float s2 = sgnf(g[j + 2] * (v2 - mu[j + 2]) * rs[j + 2] + b[j + 2]);
    float s3 = sgnf(g[j + 3] * (v3 - mu[j + 3]) * rs[j + 3] + b[j + 3]);
    *(__half2*)&a[e0]     = __floats2half2_rn(s0, s1);
    *(__half2*)&a[e0 + 2] = __floats2half2_rn(s2, s3);
}

// ---------------- host orchestration --------------------------------------------
extern "C" void kernel_launch(void* const* d_in, const int* in_sizes, int n_in,
                              void* d_out, int out_size) {
    const float* x     = (const float*)d_in[0];
    const float* W1    = (const float*)d_in[2];
    const float* g1    = (const float*)d_in[3];
    const float* b1    = (const float*)d_in[4];
    const float* W2    = (const float*)d_in[5];
    const float* g2    = (const float*)d_in[6];
    const float* b2    = (const float*)d_in[7];
    const float* W3    = (const float*)d_in[8];
    const float* g3    = (const float*)d_in[9];
    const float* b3    = (const float*)d_in[10];
    const float* W4    = (const float*)d_in[11];
    const float* scale = (const float*)d_in[12];
    float* y = (float*)d_out;

    __nv_bfloat16 *xt3, *w1b;
    __half *w2b, *w3b, *w4b, *a;
    float *h, *mu, *rs, *ps, *pq;
    cudaGetSymbolAddress((void**)&xt3, g_xt3);
    cudaGetSymbolAddress((void**)&w1b, g_w1b);
    cudaGetSymbolAddress((void**)&w2b, g_w2b);
    cudaGetSymbolAddress((void**)&w3b, g_w3b);
    cudaGetSymbolAddress((void**)&w4b, g_w4b);
    cudaGetSymbolAddress((void**)&h,   g_h);
    cudaGetSymbolAddress((void**)&a,   g_a);
    cudaGetSymbolAddress((void**)&mu,  g_mu);
    cudaGetSymbolAddress((void**)&rs,  g_rs);
    cudaGetSymbolAddress((void**)&ps,  g_ps);
    cudaGetSymbolAddress((void**)&pq,  g_pq);
    __half* h16 = (__half*)h;

    cudaFuncSetAttribute(gemm_bf16,   cudaFuncAttributeMaxDynamicSharedMemorySize, SMEM_DYN);
    cudaFuncSetAttribute(gemm_f16<0>, cudaFuncAttributeMaxDynamicSharedMemorySize, SMEM_DYN);
    cudaFuncSetAttribute(gemm_f16<1>, cudaFuncAttributeMaxDynamicSharedMemorySize, SMEM_DYN);

    // prep
    transpose_split<<<dim3(TD / 32, FIN / 32, NB), dim3(32, 8)>>>(x, xt3);
    binw3<<<(HD * FIN / 4 + 255) / 256, 256>>>(W1, w1b);
    binw_f16<<<(HD * HD / 4 + 255) / 256, 256>>>(W2, w2b, HD * HD / 4);
    binw_f16<<<(HD * HD / 4 + 255) / 256, 256>>>(W3, w3b, HD * HD / 4);
    binw_f16<<<(FIN * HD / 4 + 255) / 256, 256>>>(W4, w4b, FIN * HD / 4);

    dim3 blk(256);
    dim3 gridStats(HD / 32, 8);
    dim3 gridSign((unsigned)(((size_t)MR * HD / 4 + 255) / 256));
    dim3 gGemm(HD / BN, MR / BM);   // (16, 64)
    dim3 gGemm4(FIN / BN, MR / BM); // (4, 64)

    // layer 1 (bf16/f32, K=1536 triple-split): h fp32
    gemm_bf16<<<gGemm, blk, SMEM_DYN>>>(xt3, w1b, h, HD, 1536);
    stats_partial_f32<<<gridStats, blk>>>(h, ps, pq);
    stats_final<<<dim3(HD / 256), blk>>>(ps, pq, mu, rs);
    sign_act_f32<<<gridSign, blk>>>(h, mu, rs, g1, b1, a);

    // layer 2 (f16/f16 exact): h fp16
    gemm_f16<0><<<gGemm, blk, SMEM_DYN>>>(a, w2b, h16, HD, HD, nullptr);
    stats_partial_f16<<<gridStats, blk>>>(h16, ps, pq);
    stats_final<<<dim3(HD / 256), blk>>>(ps, pq, mu, rs);
    sign_act_f16<<<gridSign, blk>>>(h16, mu, rs, g2, b2, a);

    // layer 3
    gemm_f16<0><<<gGemm, blk, SMEM_DYN>>>(a, w3b, h16, HD, HD, nullptr);
    stats_partial_f16<<<gridStats, blk>>>(h16, ps, pq);
    stats_final<<<dim3(HD / 256), blk>>>(ps, pq, mu, rs);
    sign_act_f16<<<gridSign, blk>>>(h16, mu, rs, g3, b3, a);

    // layer 4 (f16/f16 exact, fused scale + NFT transpose)
    gemm_f16<1><<<gGemm4, blk, SMEM_DYN>>>(a, w4b, y, FIN, HD, scale);
}

// round 7
// speedup vs baseline: 1.7750x; 1.0669x over previous
#include <cuda_runtime.h>
#include <cuda_bf16.h>
#include <cuda_fp16.h>
#include <cstdint>
#include <cstddef>

#define NB   16
#define FIN  512
#define TD   512
#define MR   8192
#define HD   2048

#define BM   128
#define BN   128
#define STAGES 4
#define TILEB (128 * 80)
#define STAGEB (2 * TILEB)
#define SMEM_DYN (STAGES * STAGEB)      // 81920 B (>= 128*132*4 = 67584 for EPI1 transpose)

// ---------------- scratch ----------------------------------------------------
__device__ __nv_bfloat16 g_xt3[(size_t)MR * 1536];
__device__ __nv_bfloat16 g_w1b[(size_t)HD * 1536];
__device__ __half g_w2b[(size_t)HD * HD];
__device__ __half g_w3b[(size_t)HD * HD];
__device__ __half g_w4b[(size_t)FIN * HD];
__device__ float  g_h[(size_t)MR * HD];   // layer1 fp32; layers 2/3 reuse as fp16
__device__ __half g_a[(size_t)MR * HD];
__device__ float g_mu[HD], g_rs[HD], g_ps[8 * HD], g_pq[8 * HD];
__device__ float g_ps2[128 * HD], g_pq2[128 * HD];   // fused-epilogue partials

__device__ __forceinline__ float sgnf(float v) {
    return (v > 0.f) ? 1.f : ((v < 0.f) ? -1.f : 0.f);
}
__device__ __forceinline__ uint32_t smem_u32(const void* p) {
    return (uint32_t)__cvta_generic_to_shared(p);
}
__device__ __forceinline__ void cp16(uint32_t dst, const void* src) {
    asm volatile("cp.async.cg.shared.global [%0], [%1], 16;" :: "r"(dst), "l"(src));
}
__device__ __forceinline__ void ldsm4(uint32_t& r0, uint32_t& r1, uint32_t& r2, uint32_t& r3,
                                      uint32_t a) {
    asm volatile("ldmatrix.sync.aligned.m8n8.x4.shared.b16 {%0,%1,%2,%3}, [%4];"
                 : "=r"(r0), "=r"(r1), "=r"(r2), "=r"(r3) : "r"(a));
}
__device__ __forceinline__ void mma_bf16_f32(float* c, const uint32_t* a, const uint32_t* b) {
    asm volatile("mma.sync.aligned.m16n8k16.row.col.f32.bf16.bf16.f32 "
                 "{%0,%1,%2,%3},{%4,%5,%6,%7},{%8,%9},{%0,%1,%2,%3};"
                 : "+f"(c[0]), "+f"(c[1]), "+f"(c[2]), "+f"(c[3])
                 : "r"(a[0]), "r"(a[1]), "r"(a[2]), "r"(a[3]), "r"(b[0]), "r"(b[1]));
}
__device__ __forceinline__ void mma_f16_f16(uint32_t* c, const uint32_t* a, const uint32_t* b) {
    asm volatile("mma.sync.aligned.m16n8k16.row.col.f16.f16.f16.f16 "
                 "{%0,%1},{%2,%3,%4,%5},{%6,%7},{%0,%1};"
                 : "+r"(c[0]), "+r"(c[1])
                 : "r"(a[0]), "r"(a[1]), "r"(a[2]), "r"(a[3]), "r"(b[0]), "r"(b[1]));
}

// ---------------- tile loader (byte-geometry: 128 rows x 64B) ------------------
__device__ __forceinline__ void load_stage(
    const char* __restrict__ A, const char* __restrict__ B,
    size_t Kb, int bm, int bn, uint32_t smbase, int tid, int stage, int kc)
{
    uint32_t sA = smbase + stage * STAGEB;
    uint32_t sB = sA + TILEB;
    const char* gA = A + (size_t)bm * Kb + (size_t)kc * 64;
    const char* gB = B + (size_t)bn * Kb + (size_t)kc * 64;
#pragma unroll
    for (int i = 0; i < 2; i++) {
        int idx = tid + i * 256;
        int r = idx >> 2, c = idx & 3;
        cp16(sA + r * 80 + c * 16, gA + (size_t)r * Kb + c * 16);
    }
#pragma unroll
    for (int i = 0; i < 2; i++) {
        int idx = tid + i * 256;
        int r = idx >> 2, c = idx & 3;
        cp16(sB + r * 80 + c * 16, gB + (size_t)r * Kb + c * 16);
    }
    asm volatile("cp.async.commit_group;" ::: "memory");
}

// ---------------- bf16/f32 GEMM (layer 1) — unchanged from round 6 -------------
__global__ void __launch_bounds__(256, 2)
gemm_bf16(const __nv_bfloat16* __restrict__ A, const __nv_bfloat16* __restrict__ B,
          float* __restrict__ C, int N, int K)
{
    extern __shared__ char smraw[];
    const uint32_t smbase = smem_u32(smraw);
    const int tid = threadIdx.x, wid = tid >> 5, lid = tid & 31;
    const int bm = blockIdx.y * BM, bn = blockIdx.x * BN;
    const int NC = K / 32;
    const int wm = (wid & 1) * 64, wn = (wid >> 1) * 32;
    const int lr = ((lid >> 3) & 1) * 8 + (lid & 7);
    const int lc = (lid >> 4) * 8;
    const size_t Kb = (size_t)K * 2;

    float acc[4][4][4];
#pragma unroll
    for (int i = 0; i < 4; i++)
#pragma unroll
        for (int j = 0; j < 4; j++)
#pragma unroll
            for (int q = 0; q < 4; q++) acc[i][j][q] = 0.f;

#pragma unroll
    for (int pc = 0; pc < STAGES - 1; ++pc)
        load_stage((const char*)A, (const char*)B, Kb, bm, bn, smbase, tid, pc, pc);

    for (int kc = 0; kc < NC; ++kc) {
        const int st = kc & (STAGES - 1);
        asm volatile("cp.async.wait_group %0;" :: "n"(STAGES - 2) : "memory");
        __syncthreads();
        const uint32_t aBase = smbase + st * STAGEB;
        const uint32_t bBase = aBase + TILEB;
#pragma unroll
        for (int ks = 0; ks < 2; ++ks) {
            uint32_t a[4][4];
#pragma unroll
            for (int i = 0; i < 4; i++)
                ldsm4(a[i][0], a[i][1], a[i][2], a[i][3],
                      aBase + (uint32_t)(wm + i * 16 + lr) * 80 + (uint32_t)(ks * 16 + lc) * 2);
            uint32_t b[4][2];
#pragma unroll
            for (int jj = 0; jj < 2; jj++) {
                uint32_t r0, r1, r2, r3;
                ldsm4(r0, r1, r2, r3,
                      bBase + (uint32_t)(wn + jj * 16 + lr) * 80 + (uint32_t)(ks * 16 + lc) * 2);
                b[jj * 2 + 0][0] = r0; b[jj * 2 + 0][1] = r2;
                b[jj * 2 + 1][0] = r1; b[jj * 2 + 1][1] = r3;
            }
#pragma unroll
            for (int i = 0; i < 4; i++)
#pragma unroll
                for (int j = 0; j < 4; j++)
                    mma_bf16_f32(acc[i][j], a[i], b[j]);
        }
        int nk = kc + STAGES - 1;
        if (nk < NC)
            load_stage((const char*)A, (const char*)B, Kb, bm, bn, smbase, tid,
                       nk & (STAGES - 1), nk);
        else
            asm volatile("cp.async.commit_group;" ::: "memory");
    }

    const int row0 = lid >> 2, col0 = (lid & 3) * 2;
#pragma unroll
    for (int i = 0; i < 4; i++)
#pragma unroll
        for (int j = 0; j < 4; j++) {
            int m0 = bm + wm + i * 16 + row0;
            int n0 = bn + wn + j * 8 + col0;
            *(float2*)&C[(size_t)m0 * N + n0]       = make_float2(acc[i][j][0], acc[i][j][1]);
            *(float2*)&C[(size_t)(m0 + 8) * N + n0] = make_float2(acc[i][j][2], acc[i][j][3]);
        }
}

// ---------------- f16/f16 GEMM (layers 2/3/4) ----------------------------------
// EPI 0: h fp16 + fused per-warp column stats -> ps2/pq2[(by*2 + wm64)][col]
// EPI 1: y[batch, n, t] = float(acc)*scale[n] via smem transpose (coalesced)
template <int EPI>
__global__ void __launch_bounds__(256, 2)
gemm_f16(const __half* __restrict__ A, const __half* __restrict__ B,
         void* __restrict__ Cv, int N, int K, const float* __restrict__ scale,
         float* __restrict__ ps2, float* __restrict__ pq2)
{
    extern __shared__ char smraw[];
    const uint32_t smbase = smem_u32(smraw);
    const int tid = threadIdx.x, wid = tid >> 5, lid = tid & 31;
    const int bm = blockIdx.y * BM, bn = blockIdx.x * BN;
    const int NC = K / 32;
    const int wm = (wid & 1) * 64, wn = (wid >> 1) * 32;
    const int lr = ((lid >> 3) & 1) * 8 + (lid & 7);
    const int lc = (lid >> 4) * 8;
    const size_t Kb = (size_t)K * 2;

    uint32_t acc[4][4][2];
#pragma unroll
    for (int i = 0; i < 4; i++)
#pragma unroll
        for (int j = 0; j < 4; j++) { acc[i][j][0] = 0u; acc[i][j][1] = 0u; }

#pragma unroll
    for (int pc = 0; pc < STAGES - 1; ++pc)
        load_stage((const char*)A, (const char*)B, Kb, bm, bn, smbase, tid, pc, pc);

    for (int kc = 0; kc < NC; ++kc) {
        const int st = kc & (STAGES - 1);
        asm volatile("cp.async.wait_group %0;" :: "n"(STAGES - 2) : "memory");
        __syncthreads();
        const uint32_t aBase = smbase + st * STAGEB;
        const uint32_t bBase = aBase + TILEB;
#pragma unroll
        for (int ks = 0; ks < 2; ++ks) {
            uint32_t a[4][4];
#pragma unroll
            for (int i = 0; i < 4; i++)
                ldsm4(a[i][0], a[i][1], a[i][2], a[i][3],
                      aBase + (uint32_t)(wm + i * 16 + lr) * 80 + (uint32_t)(ks * 16 + lc) * 2);
            uint32_t b[4][2];
#pragma unroll
            for (int jj = 0; jj < 2; jj++) {
                uint32_t r0, r1, r2, r3;
                ldsm4(r0, r1, r2, r3,
                      bBase + (uint32_t)(wn + jj * 16 + lr) * 80 + (uint32_t)(ks * 16 + lc) * 2);
                b[jj * 2 + 0][0] = r0; b[jj * 2 + 0][1] = r2;
                b[jj * 2 + 1][0] = r1; b[jj * 2 + 1][1] = r3;
            }
#pragma unroll
            for (int i = 0; i < 4; i++)
#pragma unroll
                for (int j = 0; j < 4; j++)
                    mma_f16_f16(acc[i][j], a[i], b[j]);
        }
        int nk = kc + STAGES - 1;
        if (nk < NC)
            load_stage((const char*)A, (const char*)B, Kb, bm, bn, smbase, tid,
                       nk & (STAGES - 1), nk);
        else
            asm volatile("cp.async.commit_group;" ::: "memory");
    }

    const int row0 = lid >> 2, col0 = (lid & 3) * 2;
    if (EPI == 0) {
        __half* C = (__half*)Cv;
#pragma unroll
        for (int i = 0; i < 4; i++)
#pragma unroll
            for (int j = 0; j < 4; j++) {
                int m0 = bm + wm + i * 16 + row0;
                int n0 = bn + wn + j * 8 + col0;
                *(uint32_t*)&C[(size_t)m0 * N + n0]       = acc[i][j][0];
                *(uint32_t*)&C[(size_t)(m0 + 8) * N + n0] = acc[i][j][1];
            }
        // fused column stats: per warp, 64-row sums/sumsq (exact integers)
#pragma unroll
        for (int j = 0; j < 4; j++) {
            float s0 = 0.f, s1 = 0.f, q0 = 0.f, q1 = 0.f;
#pragma unroll
            for (int i = 0; i < 4; i++) {
                __half2 v0 = *(__half2*)&acc[i][j][0];
                __half2 v1 = *(__half2*)&acc[i][j][1];
                float a0 = __low2float(v0), b0 = __high2float(v0);
                float a1 = __low2float(v1), b1 = __high2float(v1);
                s0 += a0 + a1;  q0 += a0 * a0 + a1 * a1;
                s1 += b0 + b1;  q1 += b0 * b0 + b1 * b1;
            }
#pragma unroll
            for (int d = 4; d < 32; d <<= 1) {
                s0 += __shfl_xor_sync(0xFFFFFFFFu, s0, d);
                s1 += __shfl_xor_sync(0xFFFFFFFFu, s1, d);
                q0 += __shfl_xor_sync(0xFFFFFFFFu, q0, d);
                q1 += __shfl_xor_sync(0xFFFFFFFFu, q1, d);
            }
            if (lid < 4) {
                int prow = (int)blockIdx.y * 2 + (wid & 1);
                int col  = bn + wn + j * 8 + (lid & 3) * 2;
                *(float2*)&ps2[(size_t)prow * HD + col] = make_float2(s0, s1);
                *(float2*)&pq2[(size_t)prow * HD + col] = make_float2(q0, q1);
            }
        }
    } else {
        // smem transpose: trans[n_local][t_local], stride 132 floats
        float* trans = (float*)smraw;
        __syncthreads();   // all warps done with stage buffers
#pragma unroll
        for (int j = 0; j < 4; j++) {
            int n0 = wn + j * 8 + col0;
            float s0 = scale[bn + n0], s1 = scale[bn + n0 + 1];
#pragma unroll
            for (int i = 0; i < 4; i++) {
                int t0 = wm + i * 16 + row0;
                __half2 v0 = *(__half2*)&acc[i][j][0];
                __half2 v1 = *(__half2*)&acc[i][j][1];
                trans[n0 * 132 + t0]           = __low2float(v0) * s0;
                trans[(n0 + 1) * 132 + t0]     = __high2float(v0) * s1;
                trans[n0 * 132 + t0 + 8]       = __low2float(v1) * s0;
                trans[(n0 + 1) * 132 + t0 + 8] = __high2float(v1) * s1;
            }
        }
        __syncthreads();
        float* y = (float*)Cv;
        const int b0 = bm >> 9;            // batch (TD=512)
        const int tb = bm & 511;
        const int n = tid >> 1, half = tid & 1;
        float* yp = y + ((size_t)b0 * FIN + bn + n) * TD + tb + half * 64;
        const float* sp = trans + n * 132 + half * 64;
#pragma unroll
        for (int k = 0; k < 16; k++)
            *(float4*)&yp[k * 4] = *(const float4*)&sp[k * 4];
    }
}

// ---------------- prep kernels -------------------------------------------------
__global__ void transpose_split(const float* __restrict__ x, __nv_bfloat16* __restrict__ xt3) {
    __shared__ float tile[32][33];
    int n = blockIdx.z, t0 = blockIdx.x * 32, f0 = blockIdx.y * 32;
    const float* xp = x + (size_t)n * FIN * TD;
#pragma unroll
    for (int i = 0; i < 4; i++) {
        int f = f0 + threadIdx.y + i * 8;
        tile[threadIdx.y + i * 8][threadIdx.x] = xp[(size_t)f * TD + t0 + threadIdx.x];
    }
    __syncthreads();
#pragma unroll
    for (int i = 0; i < 4; i++) {
        int t = t0 + threadIdx.y + i * 8;
        int f = f0 + threadIdx.x;
        float v = tile[threadIdx.x][threadIdx.y + i * 8];
        __nv_bfloat16 hi = __float2bfloat16(v);
        float r1 = v - __bfloat162float(hi);
        __nv_bfloat16 md = __float2bfloat16(r1);
        float r2 = r1 - __bfloat162float(md);
        __nv_bfloat16 lo = __float2bfloat16(r2);
        size_t row = (size_t)((size_t)n * TD + t) * 1536;
        xt3[row + f] = hi;
        xt3[row + 512 + f] = md;
        xt3[row + 1024 + f] = lo;
    }
}

// fp16 binarize, 8 elems/thread
__global__ void binw_f16(const float* __restrict__ W, __half* __restrict__ o, int n8) {
    int i = blockIdx.x * 256 + threadIdx.x;
    if (i >= n8) return;
    float4 w0 = *(const float4*)&W[(size_t)i * 8];
    float4 w1 = *(const float4*)&W[(size_t)i * 8 + 4];
    __half2 p0 = __floats2half2_rn(sgnf(w0.x), sgnf(w0.y));
    __half2 p1 = __floats2half2_rn(sgnf(w0.z), sgnf(w0.w));
    __half2 p2 = __floats2half2_rn(sgnf(w1.x), sgnf(w1.y));
    __half2 p3 = __floats2half2_rn(sgnf(w1.z), sgnf(w1.w));
    uint4 v;
    v.x = *(uint32_t*)&p0; v.y = *(uint32_t*)&p1;
    v.z = *(uint32_t*)&p2; v.w = *(uint32_t*)&p3;
    *(uint4*)&o[(size_t)i * 8] = v;
}
// W1 (HD,512) -> bf16 (HD,1536), replicated 3x along K, 8 elems/thread
__global__ void binw3(const float* __restrict__ W1, __nv_bfloat16* __restrict__ o) {
    int i = blockIdx.x * 256 + threadIdx.x;
    if (i >= HD * FIN / 8) return;
    float4 w0 = *(const float4*)&W1[(size_t)i * 8];
    float4 w1 = *(const float4*)&W1[(size_t)i * 8 + 4];
    int row = (i * 8) >> 9, k = (i * 8) & 511;
    __nv_bfloat162 p0, p1, p2, p3;
    p0.x = __float2bfloat16(sgnf(w0.x)); p0.y = __float2bfloat16(sgnf(w0.y));
    p1.x = __float2bfloat16(sgnf(w0.z)); p1.y = __float2bfloat16(sgnf(w0.w));
    p2.x = __float2bfloat16(sgnf(w1.x)); p2.y = __float2bfloat16(sgnf(w1.y));
    p3.x = __float2bfloat16(sgnf(w1.z)); p3.y = __float2bfloat16(sgnf(w1.w));
    uint4 v;
    v.x = *(uint32_t*)&p0; v.y = *(uint32_t*)&p1;
    v.z = *(uint32_t*)&p2; v.w = *(uint32_t*)&p3;
    size_t base = (size_t)row * 1536 + k;
    *(uint4*)&o[base] = v; *(uint4*)&o[base + 512] = v; *(uint4*)&o[base + 1024] = v;
}

// ---------------- BN stats: layer-1 path (BYTE-IDENTICAL to round 6) -----------
__global__ void stats_partial_f32(const float* __restrict__ h,
                                  float* __restrict__ ps, float* __restrict__ pq) {
    int c = threadIdx.x & 31, lane = threadIdx.x >> 5;
    int col = blockIdx.x * 32 + c;
    int r0 = blockIdx.y * (MR / 8);
    float s = 0.f, sq = 0.f;
    for (int i = lane; i < MR / 8; i += 8) {
        float v = h[(size_t)(r0 + i) * HD + col];
        s += v; sq += v * v;
    }
    __shared__ float ss[8][33], sv[8][33];
    ss[lane][c] = s; sv[lane][c] = sq;
    __syncthreads();
    if (lane == 0) {
        float ts = 0.f, tq = 0.f;
#pragma unroll
        for (int l = 0; l < 8; l++) { ts += ss[l][c]; tq += sv[l][c]; }
        ps[blockIdx.y * HD + col] = ts;
        pq[blockIdx.y * HD + col] = tq;
    }
}
__global__ void stats_final(const float* __restrict__ ps, const float* __restrict__ pq,
                            float* __restrict__ mu, float* __restrict__ rs) {
    int col = blockIdx.x * 256 + threadIdx.x;
    if (col >= HD) return;
    float s = 0.f, sq = 0.f;
#pragma unroll
    for (int p = 0; p < 8; p++) { s += ps[p * HD + col]; sq += pq[p * HD + col]; }
    float m = s * (1.f / MR);
    float var = sq * (1.f / MR) - m * m;
    if (var < 0.f) var = 0.f;
    mu[col] = m;
    rs[col] = rsqrtf(var + 1e-5f);
}
// 128-partial reduce for fused-epilogue stats (layers 2/3; exact-integer sums)
__global__ void stats_final128(const float* __restrict__ ps2, const float* __restrict__ pq2,
                               float* __restrict__ mu, float* __restrict__ rs) {
    int col = blockIdx.x * 256 + threadIdx.x;
    if (col >= HD) return;
    float s = 0.f, sq = 0.f;
    for (int p = 0; p < 128; p++) { s += ps2[(size_t)p * HD + col]; sq += pq2[(size_t)p * HD + col]; }
    float m = s * (1.f / MR);
    float var = sq * (1.f / MR) - m * m;
    if (var < 0.f) var = 0.f;
    mu[col] = m;
    rs[col] = rsqrtf(var + 1e-5f);
}

// ---------------- sign activation -> fp16 (widened) -----------------------------
__global__ void sign_act_f32(const float* __restrict__ h,
                             const float* __restrict__ mu, const float* __restrict__ rs,
                             const float* __restrict__ g, const float* __restrict__ b,
                             __half* __restrict__ a) {
    size_t i8 = (size_t)blockIdx.x * blockDim.x + threadIdx.x;
    size_t e0 = i8 * 8;
    if (e0 >= (size_t)MR * HD) return;
    int j = (int)(e0 % HD);
    float4 h0 = *(const float4*)&h[e0];
    float4 h1 = *(const float4*)&h[e0 + 4];
    float4 m0 = *(const float4*)&mu[j], m1 = *(const float4*)&mu[j + 4];
    float4 r0 = *(const float4*)&rs[j], r1 = *(const float4*)&rs[j + 4];
    float4 g0 = *(const float4*)&g[j],  g1 = *(const float4*)&g[j + 4];
    float4 b0 = *(const float4*)&b[j],  b1 = *(const float4*)&b[j + 4];
    __half2 p0 = __floats2half2_rn(sgnf(g0.x * (h0.x - m0.x) * r0.x + b0.x),
                                   sgnf(g0.y * (h0.y - m0.y) * r0.y + b0.y));
    __half2 p1 = __floats2half2_rn(sgnf(g0.z * (h0.z - m0.z) * r0.z + b0.z),
                                   sgnf(g0.w * (h0.w - m0.w) * r0.w + b0.w));
    __half2 p2 = __floats2half2_rn(sgnf(g1.x * (h1.x - m1.x) * r1.x + b1.x),
                                   sgnf(g1.y * (h1.y - m1.y) * r1.y + b1.y));
    __half2 p3 = __floats2half2_rn(sgnf(g1.z * (h1.z - m1.z) * r1.z + b1.z),
                                   sgnf(g1.w * (h1.w - m1.w) * r1.w + b1.w));
    uint4 v;
    v.x = *(uint32_t*)&p0; v.y = *(uint32_t*)&p1;
    v.z = *(uint32_t*)&p2; v.w = *(uint32_t*)&p3;
    *(uint4*)&a[e0] = v;
}
__global__ void sign_act_f16(const __half* __restrict__ h,
                             const float* __restrict__ mu, const float* __restrict__ rs,
                             const float* __restrict__ g, const float* __restrict__ b,
                             __half* __restrict__ a) {
    size_t i8 = (size_t)blockIdx.x * blockDim.x + threadIdx.x;
    size_t e0 = i8 * 8;
    if (e0 >= (size_t)MR * HD) return;
    int j = (int)(e0 % HD);
    uint4 hv = *(const uint4*)&h[e0];
    const __half2* hp = (const __half2*)&hv;
    float4 m0 = *(const float4*)&mu[j], m1 = *(const float4*)&mu[j + 4];
    float4 r0 = *(const float4*)&rs[j], r1 = *(const float4*)&rs[j + 4];
    float4 g0 = *(const float4*)&g[j],  g1 = *(const float4*)&g[j + 4];
    float4 b0 = *(const float4*)&b[j],  b1 = *(const float4*)&b[j + 4];
    __half2 p0 = __floats2half2_rn(
        sgnf(g0.x * (__low2float(hp[0]) - m0.x) * r0.x + b0.x),
        sgnf(g0.y * (__high2float(hp[0]) - m0.y) * r0.y + b0.y));
    __half2 p1 = __floats2half2_rn(
        sgnf(g0.z * (__low2float(hp[1]) - m0.z) * r0.z + b0.z),
        sgnf(g0.w * (__high2float(hp[1]) - m0.w) * r0.w + b0.w));
    __half2 p2 = __floats2half2_rn(
        sgnf(g1.x * (__low2float(hp[2]) - m1.x) * r1.x + b1.x),
        sgnf(g1.y * (__high2float(hp[2]) - m1.y) * r1.y + b1.y));
    __half2 p3 = __floats2half2_rn(
        sgnf(g1.z * (__low2float(hp[3]) - m1.z) * r1.z + b1.z),
        sgnf(g1.w * (__high2float(hp[3]) - m1.w) * r1.w + b1.w));
    uint4 v;
    v.x = *(uint32_t*)&p0; v.y = *(uint32_t*)&p1;
    v.z = *(uint32_t*)&p2; v.w = *(uint32_t*)&p3;
    *(uint4*)&a[e0] = v;
}

// ---------------- host orchestration --------------------------------------------
extern "C" void kernel_launch(void* const* d_in, const int* in_sizes, int n_in,
                              void* d_out, int out_size) {
    const float* x     = (const float*)d_in[0];
    const float* W1    = (const float*)d_in[2];
    const float* g1    = (const float*)d_in[3];
    const float* b1    = (const float*)d_in[4];
    const float* W2    = (const float*)d_in[5];
    const float* g2    = (const float*)d_in[6];
    const float* b2    = (const float*)d_in[7];
    const float* W3    = (const float*)d_in[8];
    const float* g3    = (const float*)d_in[9];
    const float* b3    = (const float*)d_in[10];
    const float* W4    = (const float*)d_in[11];
    const float* scale = (const float*)d_in[12];
    float* y = (float*)d_out;

    __nv_bfloat16 *xt3, *w1b;
    __half *w2b, *w3b, *w4b, *a;
    float *h, *mu, *rs, *ps, *pq, *ps2, *pq2;
    cudaGetSymbolAddress((void**)&xt3, g_xt3);
    cudaGetSymbolAddress((void**)&w1b, g_w1b);
    cudaGetSymbolAddress((void**)&w2b, g_w2b);
    cudaGetSymbolAddress((void**)&w3b, g_w3b);
    cudaGetSymbolAddress((void**)&w4b, g_w4b);
    cudaGetSymbolAddress((void**)&h,   g_h);
    cudaGetSymbolAddress((void**)&a,   g_a);
    cudaGetSymbolAddress((void**)&mu,  g_mu);
    cudaGetSymbolAddress((void**)&rs,  g_rs);
    cudaGetSymbolAddress((void**)&ps,  g_ps);
    cudaGetSymbolAddress((void**)&pq,  g_pq);
    cudaGetSymbolAddress((void**)&ps2, g_ps2);
    cudaGetSymbolAddress((void**)&pq2, g_pq2);
    __half* h16 = (__half*)h;

    cudaFuncSetAttribute(gemm_bf16,   cudaFuncAttributeMaxDynamicSharedMemorySize, SMEM_DYN);
    cudaFuncSetAttribute(gemm_f16<0>, cudaFuncAttributeMaxDynamicSharedMemorySize, SMEM_DYN);
    cudaFuncSetAttribute(gemm_f16<1>, cudaFuncAttributeMaxDynamicSharedMemorySize, SMEM_DYN);

    // prep
    transpose_split<<<dim3(TD / 32, FIN / 32, NB), dim3(32, 8)>>>(x, xt3);
    binw3<<<(HD * FIN / 8 + 255) / 256, 256>>>(W1, w1b);
    binw_f16<<<(HD * HD / 8 + 255) / 256, 256>>>(W2, w2b, HD * HD / 8);
    binw_f16<<<(HD * HD / 8 + 255) / 256, 256>>>(W3, w3b, HD * HD / 8);
    binw_f16<<<(FIN * HD / 8 + 255) / 256, 256>>>(W4, w4b, FIN * HD / 8);

    dim3 blk(256);
    dim3 gridStats(HD / 32, 8);
    dim3 gridSign((unsigned)(((size_t)MR * HD / 8 + 255) / 256));
    dim3 gGemm(HD / BN, MR / BM);   // (16, 64)
    dim3 gGemm4(FIN / BN, MR / BM); // (4, 64)

    // layer 1 (bf16/f32, K=1536): h fp32; stats path byte-identical to round 6
    gemm_bf16<<<gGemm, blk, SMEM_DYN>>>(xt3, w1b, h, HD, 1536);
    stats_partial_f32<<<gridStats, blk>>>(h, ps, pq);
    stats_final<<<dim3(HD / 256), blk>>>(ps, pq, mu, rs);
    sign_act_f32<<<gridSign, blk>>>(h, mu, rs, g1, b1, a);

    // layer 2 (f16/f16 exact, fused stats)
    gemm_f16<0><<<gGemm, blk, SMEM_DYN>>>(a, w2b, h16, HD, HD, nullptr, ps2, pq2);
    stats_final128<<<dim3(HD / 256), blk>>>(ps2, pq2, mu, rs);
    sign_act_f16<<<gridSign, blk>>>(h16, mu, rs, g2, b2, a);

    // layer 3
    gemm_f16<0><<<gGemm, blk, SMEM_DYN>>>(a, w3b, h16, HD, HD, nullptr, ps2, pq2);
    stats_final128<<<dim3(HD / 256), blk>>>(ps2, pq2, mu, rs);
    sign_act_f16<<<gridSign, blk>>>(h16, mu, rs, g3, b3, a);

    // layer 4 (f16/f16 exact, fused scale + coalesced smem-transpose store)
    gemm_f16<1><<<gGemm4, blk, SMEM_DYN>>>(a, w4b, y, FIN, HD, scale, nullptr, nullptr);
}

// round 8
// speedup vs baseline: 1.9206x; 1.0820x over previous
#include <cuda_runtime.h>
#include <cuda_fp16.h>
#include <cstdint>
#include <cstddef>

#define NB   16
#define FIN  512
#define TD   512
#define MR   8192
#define HD   2048

#define BM   128
#define BN   128
#define STAGES 4
#define TILEB (128 * 80)
#define STAGEB (2 * TILEB)
#define SMEM_DYN (STAGES * STAGEB)      // 81920 B (>= 128*132*4 for EPI1 transpose)

// ---------------- scratch ----------------------------------------------------
__device__ __half g_xt2[(size_t)MR * 1024];            // x 2-way f16 split, (M,1024)
__device__ __half g_w1b[(size_t)HD * 1024];            // sgn(W1) replicated 2x
__device__ __half g_wb[(size_t)2 * HD * HD + (size_t)FIN * HD];  // W2|W3|W4 binarized
__device__ float  g_h[(size_t)MR * HD];                // layer1 fp32; layers 2/3 as fp16
__device__ __half g_a[(size_t)MR * HD];
__device__ float g_mu[HD], g_rs[HD], g_ps[8 * HD], g_pq[8 * HD];
__device__ float g_ps2[128 * HD], g_pq2[128 * HD];

__device__ __forceinline__ float sgnf(float v) {
    return (v > 0.f) ? 1.f : ((v < 0.f) ? -1.f : 0.f);
}
__device__ __forceinline__ uint32_t smem_u32(const void* p) {
    return (uint32_t)__cvta_generic_to_shared(p);
}
__device__ __forceinline__ void cp16(uint32_t dst, const void* src) {
    asm volatile("cp.async.cg.shared.global [%0], [%1], 16;" :: "r"(dst), "l"(src));
}
__device__ __forceinline__ void ldsm4(uint32_t& r0, uint32_t& r1, uint32_t& r2, uint32_t& r3,
                                      uint32_t a) {
    asm volatile("ldmatrix.sync.aligned.m8n8.x4.shared.b16 {%0,%1,%2,%3}, [%4];"
                 : "=r"(r0), "=r"(r1), "=r"(r2), "=r"(r3) : "r"(a));
}
__device__ __forceinline__ void mma_f16_f32(float* c, const uint32_t* a, const uint32_t* b) {
    asm volatile("mma.sync.aligned.m16n8k16.row.col.f32.f16.f16.f32 "
                 "{%0,%1,%2,%3},{%4,%5,%6,%7},{%8,%9},{%0,%1,%2,%3};"
                 : "+f"(c[0]), "+f"(c[1]), "+f"(c[2]), "+f"(c[3])
                 : "r"(a[0]), "r"(a[1]), "r"(a[2]), "r"(a[3]), "r"(b[0]), "r"(b[1]));
}
__device__ __forceinline__ void mma_f16_f16(uint32_t* c, const uint32_t* a, const uint32_t* b) {
    asm volatile("mma.sync.aligned.m16n8k16.row.col.f16.f16.f16.f16 "
                 "{%0,%1},{%2,%3,%4,%5},{%6,%7},{%0,%1};"
                 : "+r"(c[0]), "+r"(c[1])
                 : "r"(a[0]), "r"(a[1]), "r"(a[2]), "r"(a[3]), "r"(b[0]), "r"(b[1]));
}

// ---------------- tile loader (byte-geometry: 128 rows x 64B) ------------------
__device__ __forceinline__ void load_stage(
    const char* __restrict__ A, const char* __restrict__ B,
    size_t Kb, int bm, int bn, uint32_t smbase, int tid, int stage, int kc)
{
    uint32_t sA = smbase + stage * STAGEB;
    uint32_t sB = sA + TILEB;
    const char* gA = A + (size_t)bm * Kb + (size_t)kc * 64;
    const char* gB = B + (size_t)bn * Kb + (size_t)kc * 64;
#pragma unroll
    for (int i = 0; i < 2; i++) {
        int idx = tid + i * 256;
        int r = idx >> 2, c = idx & 3;
        cp16(sA + r * 80 + c * 16, gA + (size_t)r * Kb + c * 16);
    }
#pragma unroll
    for (int i = 0; i < 2; i++) {
        int idx = tid + i * 256;
        int r = idx >> 2, c = idx & 3;
        cp16(sB + r * 80 + c * 16, gB + (size_t)r * Kb + c * 16);
    }
    asm volatile("cp.async.commit_group;" ::: "memory");
}

// ---------------- f16-in / f32-acc GEMM (layer 1): h fp32 = A @ B^T ------------
__global__ void __launch_bounds__(256, 2)
gemm_l1(const __half* __restrict__ A, const __half* __restrict__ B,
        float* __restrict__ C, int N, int K)
{
    extern __shared__ char smraw[];
    const uint32_t smbase = smem_u32(smraw);
    const int tid = threadIdx.x, wid = tid >> 5, lid = tid & 31;
    const int bm = blockIdx.y * BM, bn = blockIdx.x * BN;
    const int NC = K / 32;
    const int wm = (wid & 1) * 64, wn = (wid >> 1) * 32;
    const int lr = ((lid >> 3) & 1) * 8 + (lid & 7);
    const int lc = (lid >> 4) * 8;
    const size_t Kb = (size_t)K * 2;

    float acc[4][4][4];
#pragma unroll
    for (int i = 0; i < 4; i++)
#pragma unroll
        for (int j = 0; j < 4; j++)
#pragma unroll
            for (int q = 0; q < 4; q++) acc[i][j][q] = 0.f;

#pragma unroll
    for (int pc = 0; pc < STAGES - 1; ++pc)
        load_stage((const char*)A, (const char*)B, Kb, bm, bn, smbase, tid, pc, pc);

    for (int kc = 0; kc < NC; ++kc) {
        const int st = kc & (STAGES - 1);
        asm volatile("cp.async.wait_group %0;" :: "n"(STAGES - 2) : "memory");
        __syncthreads();
        const uint32_t aBase = smbase + st * STAGEB;
        const uint32_t bBase = aBase + TILEB;
#pragma unroll
        for (int ks = 0; ks < 2; ++ks) {
            uint32_t a[4][4];
#pragma unroll
            for (int i = 0; i < 4; i++)
                ldsm4(a[i][0], a[i][1], a[i][2], a[i][3],
                      aBase + (uint32_t)(wm + i * 16 + lr) * 80 + (uint32_t)(ks * 16 + lc) * 2);
            uint32_t b[4][2];
#pragma unroll
            for (int jj = 0; jj < 2; jj++) {
                uint32_t r0, r1, r2, r3;
                ldsm4(r0, r1, r2, r3,
                      bBase + (uint32_t)(wn + jj * 16 + lr) * 80 + (uint32_t)(ks * 16 + lc) * 2);
                b[jj * 2 + 0][0] = r0; b[jj * 2 + 0][1] = r2;
                b[jj * 2 + 1][0] = r1; b[jj * 2 + 1][1] = r3;
            }
#pragma unroll
            for (int i = 0; i < 4; i++)
#pragma unroll
                for (int j = 0; j < 4; j++)
                    mma_f16_f32(acc[i][j], a[i], b[j]);
        }
        int nk = kc + STAGES - 1;
        if (nk < NC)
            load_stage((const char*)A, (const char*)B, Kb, bm, bn, smbase, tid,
                       nk & (STAGES - 1), nk);
        else
            asm volatile("cp.async.commit_group;" ::: "memory");
    }

    const int row0 = lid >> 2, col0 = (lid & 3) * 2;
#pragma unroll
    for (int i = 0; i < 4; i++)
#pragma unroll
        for (int j = 0; j < 4; j++) {
            int m0 = bm + wm + i * 16 + row0;
            int n0 = bn + wn + j * 8 + col0;
            *(float2*)&C[(size_t)m0 * N + n0]       = make_float2(acc[i][j][0], acc[i][j][1]);
            *(float2*)&C[(size_t)(m0 + 8) * N + n0] = make_float2(acc[i][j][2], acc[i][j][3]);
        }
}

// ---------------- f16/f16 GEMM (layers 2/3/4) ----------------------------------
// EPI 0: h fp16 + fused per-warp column stats.  EPI 1: scaled + transposed store.
template <int EPI>
__global__ void __launch_bounds__(256, 2)
gemm_f16(const __half* __restrict__ A, const __half* __restrict__ B,
         void* __restrict__ Cv, int N, int K, const float* __restrict__ scale,
         float* __restrict__ ps2, float* __restrict__ pq2)
{
    extern __shared__ char smraw[];
    const uint32_t smbase = smem_u32(smraw);
    const int tid = threadIdx.x, wid = tid >> 5, lid = tid & 31;
    const int bm = blockIdx.y * BM, bn = blockIdx.x * BN;
    const int NC = K / 32;
    const int wm = (wid & 1) * 64, wn = (wid >> 1) * 32;
    const int lr = ((lid >> 3) & 1) * 8 + (lid & 7);
    const int lc = (lid >> 4) * 8;
    const size_t Kb = (size_t)K * 2;

    uint32_t acc[4][4][2];
#pragma unroll
    for (int i = 0; i < 4; i++)
#pragma unroll
        for (int j = 0; j < 4; j++) { acc[i][j][0] = 0u; acc[i][j][1] = 0u; }

#pragma unroll
    for (int pc = 0; pc < STAGES - 1; ++pc)
        load_stage((const char*)A, (const char*)B, Kb, bm, bn, smbase, tid, pc, pc);

    for (int kc = 0; kc < NC; ++kc) {
        const int st = kc & (STAGES - 1);
        asm volatile("cp.async.wait_group %0;" :: "n"(STAGES - 2) : "memory");
        __syncthreads();
        const uint32_t aBase = smbase + st * STAGEB;
        const uint32_t bBase = aBase + TILEB;
#pragma unroll
        for (int ks = 0; ks < 2; ++ks) {
            uint32_t a[4][4];
#pragma unroll
            for (int i = 0; i < 4; i++)
                ldsm4(a[i][0], a[i][1], a[i][2], a[i][3],
                      aBase + (uint32_t)(wm + i * 16 + lr) * 80 + (uint32_t)(ks * 16 + lc) * 2);
            uint32_t b[4][2];
#pragma unroll
            for (int jj = 0; jj < 2; jj++) {
                uint32_t r0, r1, r2, r3;
                ldsm4(r0, r1, r2, r3,
                      bBase + (uint32_t)(wn + jj * 16 + lr) * 80 + (uint32_t)(ks * 16 + lc) * 2);
                b[jj * 2 + 0][0] = r0; b[jj * 2 + 0][1] = r2;
                b[jj * 2 + 1][0] = r1; b[jj * 2 + 1][1] = r3;
            }
#pragma unroll
            for (int i = 0; i < 4; i++)
#pragma unroll
                for (int j = 0; j < 4; j++)
                    mma_f16_f16(acc[i][j], a[i], b[j]);
        }
        int nk = kc + STAGES - 1;
        if (nk < NC)
            load_stage((const char*)A, (const char*)B, Kb, bm, bn, smbase, tid,
                       nk & (STAGES - 1), nk);
        else
            asm volatile("cp.async.commit_group;" ::: "memory");
    }

    const int row0 = lid >> 2, col0 = (lid & 3) * 2;
    if (EPI == 0) {
        __half* C = (__half*)Cv;
#pragma unroll
        for (int i = 0; i < 4; i++)
#pragma unroll
            for (int j = 0; j < 4; j++) {
                int m0 = bm + wm + i * 16 + row0;
                int n0 = bn + wn + j * 8 + col0;
                *(uint32_t*)&C[(size_t)m0 * N + n0]       = acc[i][j][0];
                *(uint32_t*)&C[(size_t)(m0 + 8) * N + n0] = acc[i][j][1];
            }
#pragma unroll
        for (int j = 0; j < 4; j++) {
            float s0 = 0.f, s1 = 0.f, q0 = 0.f, q1 = 0.f;
#pragma unroll
            for (int i = 0; i < 4; i++) {
                __half2 v0 = *(__half2*)&acc[i][j][0];
                __half2 v1 = *(__half2*)&acc[i][j][1];
                float a0 = __low2float(v0), b0 = __high2float(v0);
                float a1 = __low2float(v1), b1 = __high2float(v1);
                s0 += a0 + a1;  q0 += a0 * a0 + a1 * a1;
                s1 += b0 + b1;  q1 += b0 * b0 + b1 * b1;
            }
#pragma unroll
            for (int d = 4; d < 32; d <<= 1) {
                s0 += __shfl_xor_sync(0xFFFFFFFFu, s0, d);
                s1 += __shfl_xor_sync(0xFFFFFFFFu, s1, d);
                q0 += __shfl_xor_sync(0xFFFFFFFFu, q0, d);
                q1 += __shfl_xor_sync(0xFFFFFFFFu, q1, d);
            }
            if (lid < 4) {
                int prow = (int)blockIdx.y * 2 + (wid & 1);
                int col  = bn + wn + j * 8 + (lid & 3) * 2;
                *(float2*)&ps2[(size_t)prow * HD + col] = make_float2(s0, s1);
                *(float2*)&pq2[(size_t)prow * HD + col] = make_float2(q0, q1);
            }
        }
    } else {
        float* trans = (float*)smraw;
        __syncthreads();
#pragma unroll
        for (int j = 0; j < 4; j++) {
            int n0 = wn + j * 8 + col0;
            float s0 = scale[bn + n0], s1 = scale[bn + n0 + 1];
#pragma unroll
            for (int i = 0; i < 4; i++) {
                int t0 = wm + i * 16 + row0;
                __half2 v0 = *(__half2*)&acc[i][j][0];
                __half2 v1 = *(__half2*)&acc[i][j][1];
                trans[n0 * 132 + t0]           = __low2float(v0) * s0;
                trans[(n0 + 1) * 132 + t0]     = __high2float(v0) * s1;
                trans[n0 * 132 + t0 + 8]       = __low2float(v1) * s0;
                trans[(n0 + 1) * 132 + t0 + 8] = __high2float(v1) * s1;
            }
        }
        __syncthreads();
        float* y = (float*)Cv;
        const int b0 = bm >> 9;
        const int tb = bm & 511;
        const int n = tid >> 1, half = tid & 1;
        float* yp = y + ((size_t)b0 * FIN + bn + n) * TD + tb + half * 64;
        const float* sp = trans + n * 132 + half * 64;
#pragma unroll
        for (int k = 0; k < 16; k++)
            *(float4*)&yp[k * 4] = *(const float4*)&sp[k * 4];
    }
}

// ---------------- prep kernels -------------------------------------------------
// x (N,F,T) fp32 -> xt2 (N*T, 1024) f16 two-way split [hi | lo]
__global__ void transpose_split2(const float* __restrict__ x, __half* __restrict__ xt2) {
    __shared__ float tile[32][33];
    int n = blockIdx.z, t0 = blockIdx.x * 32, f0 = blockIdx.y * 32;
    const float* xp = x + (size_t)n * FIN * TD;
#pragma unroll
    for (int i = 0; i < 4; i++) {
        int f = f0 + threadIdx.y + i * 8;
        tile[threadIdx.y + i * 8][threadIdx.x] = xp[(size_t)f * TD + t0 + threadIdx.x];
    }
    __syncthreads();
#pragma unroll
    for (int i = 0; i < 4; i++) {
        int t = t0 + threadIdx.y + i * 8;
        int f = f0 + threadIdx.x;
        float v = tile[threadIdx.x][threadIdx.y + i * 8];
        __half hi = __float2half_rn(v);
        float r1 = v - __half2float(hi);
        __half lo = __float2half_rn(r1);
        size_t row = (size_t)((size_t)n * TD + t) * 1024;
        xt2[row + f] = hi;
        xt2[row + 512 + f] = lo;
    }
}

// all three weight matrices binarized in ONE launch (8 elems/thread)
__global__ void binw_all(const float* __restrict__ W2, const float* __restrict__ W3,
                         const float* __restrict__ W4, __half* __restrict__ o) {
    const int C2 = HD * HD / 8, C3 = 2 * C2, C4 = C3 + FIN * HD / 8;
    int i = blockIdx.x * 256 + threadIdx.x;
    if (i >= C4) return;
    const float* src;
    size_t off;
    if (i < C2)      { src = W2; off = (size_t)i * 8; }
    else if (i < C3) { src = W3; off = (size_t)(i - C2) * 8; }
    else             { src = W4; off = (size_t)(i - C3) * 8; }
    float4 w0 = *(const float4*)&src[off];
    float4 w1 = *(const float4*)&src[off + 4];
    __half2 p0 = __floats2half2_rn(sgnf(w0.x), sgnf(w0.y));
    __half2 p1 = __floats2half2_rn(sgnf(w0.z), sgnf(w0.w));
    __half2 p2 = __floats2half2_rn(sgnf(w1.x), sgnf(w1.y));
    __half2 p3 = __floats2half2_rn(sgnf(w1.z), sgnf(w1.w));
    uint4 v;
    v.x = *(uint32_t*)&p0; v.y = *(uint32_t*)&p1;
    v.z = *(uint32_t*)&p2; v.w = *(uint32_t*)&p3;
    *(uint4*)&o[(size_t)i * 8] = v;
}
// W1 (HD,512) -> f16 (HD,1024), replicated 2x along K
__global__ void binw1(const float* __restrict__ W1, __half* __restrict__ o) {
    int i = blockIdx.x * 256 + threadIdx.x;
    if (i >= HD * FIN / 8) return;
    float4 w0 = *(const float4*)&W1[(size_t)i * 8];
    float4 w1 = *(const float4*)&W1[(size_t)i * 8 + 4];
    int row = (i * 8) >> 9, k = (i * 8) & 511;
    __half2 p0 = __floats2half2_rn(sgnf(w0.x), sgnf(w0.y));
    __half2 p1 = __floats2half2_rn(sgnf(w0.z), sgnf(w0.w));
    __half2 p2 = __floats2half2_rn(sgnf(w1.x), sgnf(w1.y));
    __half2 p3 = __floats2half2_rn(sgnf(w1.z), sgnf(w1.w));
    uint4 v;
    v.x = *(uint32_t*)&p0; v.y = *(uint32_t*)&p1;
    v.z = *(uint32_t*)&p2; v.w = *(uint32_t*)&p3;
    size_t base = (size_t)row * 1024 + k;
    *(uint4*)&o[base] = v;
    *(uint4*)&o[base + 512] = v;
}

// ---------------- BN stats (layer-1 path unchanged) ------------------------------
__global__ void stats_partial_f32(const float* __restrict__ h,
                                  float* __restrict__ ps, float* __restrict__ pq) {
    int c = threadIdx.x & 31, lane = threadIdx.x >> 5;
    int col = blockIdx.x * 32 + c;
    int r0 = blockIdx.y * (MR / 8);
    float s = 0.f, sq = 0.f;
    for (int i = lane; i < MR / 8; i += 8) {
        float v = h[(size_t)(r0 + i) * HD + col];
        s += v; sq += v * v;
    }
    __shared__ float ss[8][33], sv[8][33];
    ss[lane][c] = s; sv[lane][c] = sq;
    __syncthreads();
    if (lane == 0) {
        float ts = 0.f, tq = 0.f;
#pragma unroll
        for (int l = 0; l < 8; l++) { ts += ss[l][c]; tq += sv[l][c]; }
        ps[blockIdx.y * HD + col] = ts;
        pq[blockIdx.y * HD + col] = tq;
    }
}
__global__ void stats_final(const float* __restrict__ ps, const float* __restrict__ pq,
                            float* __restrict__ mu, float* __restrict__ rs) {
    int col = blockIdx.x * 256 + threadIdx.x;
    if (col >= HD) return;
    float s = 0.f, sq = 0.f;
#pragma unroll
    for (int p = 0; p < 8; p++) { s += ps[p * HD + col]; sq += pq[p * HD + col]; }
    float m = s * (1.f / MR);
    float var = sq * (1.f / MR) - m * m;
    if (var < 0.f) var = 0.f;
    mu[col] = m;
    rs[col] = rsqrtf(var + 1e-5f);
}
__global__ void stats_final128(const float* __restrict__ ps2, const float* __restrict__ pq2,
                               float* __restrict__ mu, float* __restrict__ rs) {
    int col = blockIdx.x * 256 + threadIdx.x;
    if (col >= HD) return;
    float s = 0.f, sq = 0.f;
    for (int p = 0; p < 128; p++) { s += ps2[(size_t)p * HD + col]; sq += pq2[(size_t)p * HD + col]; }
    float m = s * (1.f / MR);
    float var = sq * (1.f / MR) - m * m;
    if (var < 0.f) var = 0.f;
    mu[col] = m;
    rs[col] = rsqrtf(var + 1e-5f);
}

// ---------------- sign activations ----------------------------------------------
__global__ void sign_act_f32(const float* __restrict__ h,
                             const float* __restrict__ mu, const float* __restrict__ rs,
                             const float* __restrict__ g, const float* __restrict__ b,
                             __half* __restrict__ a) {
    size_t i8 = (size_t)blockIdx.x * blockDim.x + threadIdx.x;
    size_t e0 = i8 * 8;
    if (e0 >= (size_t)MR * HD) return;
    int j = (int)(e0 % HD);
    float4 h0 = *(const float4*)&h[e0];
    float4 h1 = *(const float4*)&h[e0 + 4];
    float4 m0 = *(const float4*)&mu[j], m1 = *(const float4*)&mu[j + 4];
    float4 r0 = *(const float4*)&rs[j], r1 = *(const float4*)&rs[j + 4];
    float4 g0 = *(const float4*)&g[j],  g1 = *(const float4*)&g[j + 4];
    float4 b0 = *(const float4*)&b[j],  b1 = *(const float4*)&b[j + 4];
    __half2 p0 = __floats2half2_rn(sgnf(g0.x * (h0.x - m0.x) * r0.x + b0.x),
                                   sgnf(g0.y * (h0.y - m0.y) * r0.y + b0.y));
    __half2 p1 = __floats2half2_rn(sgnf(g0.z * (h0.z - m0.z) * r0.z + b0.z),
                                   sgnf(g0.w * (h0.w - m0.w) * r0.w + b0.w));
    __half2 p2 = __floats2half2_rn(sgnf(g1.x * (h1.x - m1.x) * r1.x + b1.x),
                                   sgnf(g1.y * (h1.y - m1.y) * r1.y + b1.y));
    __half2 p3 = __floats2half2_rn(sgnf(g1.z * (h1.z - m1.z) * r1.z + b1.z),
                                   sgnf(g1.w * (h1.w - m1.w) * r1.w + b1.w));
    uint4 v;
    v.x = *(uint32_t*)&p0; v.y = *(uint32_t*)&p1;
    v.z = *(uint32_t*)&p2; v.w = *(uint32_t*)&p3;
    *(uint4*)&a[e0] = v;
}
__global__ void sign_act_f16(const __half* __restrict__ h,
                             const float* __restrict__ mu, const float* __restrict__ rs,
                             const float* __restrict__ g, const float* __restrict__ b,
                             __half* __restrict__ a) {
    size_t i8 = (size_t)blockIdx.x * blockDim.x + threadIdx.x;
    size_t e0 = i8 * 8;
    if (e0 >= (size_t)MR * HD) return;
    int j = (int)(e0 % HD);
    uint4 hv = *(const uint4*)&h[e0];
    const __half2* hp = (const __half2*)&hv;
    float4 m0 = *(const float4*)&mu[j], m1 = *(const float4*)&mu[j + 4];
    float4 r0 = *(const float4*)&rs[j], r1 = *(const float4*)&rs[j + 4];
    float4 g0 = *(const float4*)&g[j],  g1 = *(const float4*)&g[j + 4];
    float4 b0 = *(const float4*)&b[j],  b1 = *(const float4*)&b[j + 4];
    __half2 p0 = __floats2half2_rn(
        sgnf(g0.x * (__low2float(hp[0]) - m0.x) * r0.x + b0.x),
        sgnf(g0.y * (__high2float(hp[0]) - m0.y) * r0.y + b0.y));
    __half2 p1 = __floats2half2_rn(
        sgnf(g0.z * (__low2float(hp[1]) - m0.z) * r0.z + b0.z),
        sgnf(g0.w * (__high2float(hp[1]) - m0.w) * r0.w + b0.w));
    __half2 p2 = __floats2half2_rn(
        sgnf(g1.x * (__low2float(hp[2]) - m1.x) * r1.x + b1.x),
        sgnf(g1.y * (__high2float(hp[2]) - m1.y) * r1.y + b1.y));
    __half2 p3 = __floats2half2_rn(
        sgnf(g1.z * (__low2float(hp[3]) - m1.z) * r1.z + b1.z),
        sgnf(g1.w * (__high2float(hp[3]) - m1.w) * r1.w + b1.w));
    uint4 v;
    v.x = *(uint32_t*)&p0; v.y = *(uint32_t*)&p1;
    v.z = *(uint32_t*)&p2; v.w = *(uint32_t*)&p3;
    *(uint4*)&a[e0] = v;
}

// ---------------- host orchestration --------------------------------------------
extern "C" void kernel_launch(void* const* d_in, const int* in_sizes, int n_in,
                              void* d_out, int out_size) {
    const float* x     = (const float*)d_in[0];
    const float* W1    = (const float*)d_in[2];
    const float* g1    = (const float*)d_in[3];
    const float* b1    = (const float*)d_in[4];
    const float* W2    = (const float*)d_in[5];
    const float* g2    = (const float*)d_in[6];
    const float* b2    = (const float*)d_in[7];
    const float* W3    = (const float*)d_in[8];
    const float* g3    = (const float*)d_in[9];
    const float* b3    = (const float*)d_in[10];
    const float* W4    = (const float*)d_in[11];
    const float* scale = (const float*)d_in[12];
    float* y = (float*)d_out;

    __half *xt2, *w1b, *wb, *a;
    float *h, *mu, *rs, *ps, *pq, *ps2, *pq2;
    cudaGetSymbolAddress((void**)&xt2, g_xt2);
    cudaGetSymbolAddress((void**)&w1b, g_w1b);
    cudaGetSymbolAddress((void**)&wb,  g_wb);
    cudaGetSymbolAddress((void**)&h,   g_h);
    cudaGetSymbolAddress((void**)&a,   g_a);
    cudaGetSymbolAddress((void**)&mu,  g_mu);
    cudaGetSymbolAddress((void**)&rs,  g_rs);
    cudaGetSymbolAddress((void**)&ps,  g_ps);
    cudaGetSymbolAddress((void**)&pq,  g_pq);
    cudaGetSymbolAddress((void**)&ps2, g_ps2);
    cudaGetSymbolAddress((void**)&pq2, g_pq2);
    __half* h16 = (__half*)h;
    __half* w2b = wb;
    __half* w3b = wb + (size_t)HD * HD;
    __half* w4b = wb + (size_t)2 * HD * HD;

    cudaFuncSetAttribute(gemm_l1,     cudaFuncAttributeMaxDynamicSharedMemorySize, SMEM_DYN);
    cudaFuncSetAttribute(gemm_f16<0>, cudaFuncAttributeMaxDynamicSharedMemorySize, SMEM_DYN);
    cudaFuncSetAttribute(gemm_f16<1>, cudaFuncAttributeMaxDynamicSharedMemorySize, SMEM_DYN);

    // prep
    transpose_split2<<<dim3(TD / 32, FIN / 32, NB), dim3(32, 8)>>>(x, xt2);
    binw1<<<(HD * FIN / 8 + 255) / 256, 256>>>(W1, w1b);
    {
        int chunks = (2 * HD * HD + FIN * HD) / 8;
        binw_all<<<(chunks + 255) / 256, 256>>>(W2, W3, W4, wb);
    }

    dim3 blk(256);
    dim3 gridStats(HD / 32, 8);
    dim3 gridSign((unsigned)(((size_t)MR * HD / 8 + 255) / 256));
    dim3 gGemm(HD / BN, MR / BM);   // (16, 64)
    dim3 gGemm4(FIN / BN, MR / BM); // (4, 64)

    // layer 1 (f16 2-way split, f32 accum, K=1024): h fp32
    gemm_l1<<<gGemm, blk, SMEM_DYN>>>(xt2, w1b, h, HD, 1024);
    stats_partial_f32<<<gridStats, blk>>>(h, ps, pq);
    stats_final<<<dim3(HD / 256), blk>>>(ps, pq, mu, rs);
    sign_act_f32<<<gridSign, blk>>>(h, mu, rs, g1, b1, a);

    // layer 2 (f16/f16 exact, fused stats)
    gemm_f16<0><<<gGemm, blk, SMEM_DYN>>>(a, w2b, h16, HD, HD, nullptr, ps2, pq2);
    stats_final128<<<dim3(HD / 256), blk>>>(ps2, pq2, mu, rs);
    sign_act_f16<<<gridSign, blk>>>(h16, mu, rs, g2, b2, a);

    // layer 3
    gemm_f16<0><<<gGemm, blk, SMEM_DYN>>>(a, w3b, h16, HD, HD, nullptr, ps2, pq2);
    stats_final128<<<dim3(HD / 256), blk>>>(ps2, pq2, mu, rs);
    sign_act_f16<<<gridSign, blk>>>(h16, mu, rs, g3, b3, a);

    // layer 4 (f16/f16 exact, fused scale + coalesced transpose)
    gemm_f16<1><<<gGemm4, blk, SMEM_DYN>>>(a, w4b, y, FIN, HD, scale, nullptr, nullptr);
}

// round 9
// speedup vs baseline: 2.1056x; 1.0963x over previous
#include <cuda_runtime.h>
#include <cuda_fp16.h>
#include <cstdint>
#include <cstddef>

#define NB   16
#define FIN  512
#define TD   512
#define MR   8192
#define HD   2048

#define BM   128
#define BN   128
#define STAGES 3
#define LDROW 144                        // 128B data + 16B pad
#define TILEB (128 * LDROW)              // 18432 B
#define STAGEB (2 * TILEB)               // 36864 B
#define SMEM_DYN (STAGES * STAGEB)       // 110592 B (>= 128*132*4 for EPI1 transpose)

// ---------------- scratch ----------------------------------------------------
__device__ __half g_xt2[(size_t)MR * 1024];
__device__ __half g_w1b[(size_t)HD * 1024];
__device__ __half g_wb[(size_t)2 * HD * HD + (size_t)FIN * HD];
__device__ float  g_h[(size_t)MR * HD];
__device__ __half g_a[(size_t)MR * HD];
__device__ float g_mu[HD], g_rs[HD], g_ps[8 * HD], g_pq[8 * HD];
__device__ float g_ps2[128 * HD], g_pq2[128 * HD];

__device__ __forceinline__ float sgnf(float v) {
    return (v > 0.f) ? 1.f : ((v < 0.f) ? -1.f : 0.f);
}
__device__ __forceinline__ uint32_t smem_u32(const void* p) {
    return (uint32_t)__cvta_generic_to_shared(p);
}
__device__ __forceinline__ void cp16(uint32_t dst, const void* src) {
    asm volatile("cp.async.cg.shared.global [%0], [%1], 16;" :: "r"(dst), "l"(src));
}
__device__ __forceinline__ void ldsm4(uint32_t& r0, uint32_t& r1, uint32_t& r2, uint32_t& r3,
                                      uint32_t a) {
    asm volatile("ldmatrix.sync.aligned.m8n8.x4.shared.b16 {%0,%1,%2,%3}, [%4];"
                 : "=r"(r0), "=r"(r1), "=r"(r2), "=r"(r3) : "r"(a));
}
__device__ __forceinline__ void mma_f16_f32(float* c, const uint32_t* a, const uint32_t* b) {
    asm volatile("mma.sync.aligned.m16n8k16.row.col.f32.f16.f16.f32 "
                 "{%0,%1,%2,%3},{%4,%5,%6,%7},{%8,%9},{%0,%1,%2,%3};"
                 : "+f"(c[0]), "+f"(c[1]), "+f"(c[2]), "+f"(c[3])
                 : "r"(a[0]), "r"(a[1]), "r"(a[2]), "r"(a[3]), "r"(b[0]), "r"(b[1]));
}
__device__ __forceinline__ void mma_f16_f16(uint32_t* c, const uint32_t* a, const uint32_t* b) {
    asm volatile("mma.sync.aligned.m16n8k16.row.col.f16.f16.f16.f16 "
                 "{%0,%1},{%2,%3,%4,%5},{%6,%7},{%0,%1};"
                 : "+r"(c[0]), "+r"(c[1])
                 : "r"(a[0]), "r"(a[1]), "r"(a[2]), "r"(a[3]), "r"(b[0]), "r"(b[1]));
}

// ---------------- tile loader: 128 rows x 128B of K per stage -------------------
__device__ __forceinline__ void load_stage(
    const char* __restrict__ A, const char* __restrict__ B,
    size_t Kb, int bm, int bn, uint32_t smbase, int tid, int stage, int kc)
{
    uint32_t sA = smbase + stage * STAGEB;
    uint32_t sB = sA + TILEB;
    const char* gA = A + (size_t)bm * Kb + (size_t)kc * 128;
    const char* gB = B + (size_t)bn * Kb + (size_t)kc * 128;
#pragma unroll
    for (int i = 0; i < 4; i++) {
        int idx = tid + i * 256;          // 0..1023
        int r = idx >> 3, c = idx & 7;
        cp16(sA + r * LDROW + c * 16, gA + (size_t)r * Kb + c * 16);
    }
#pragma unroll
    for (int i = 0; i < 4; i++) {
        int idx = tid + i * 256;
        int r = idx >> 3, c = idx & 7;
        cp16(sB + r * LDROW + c * 16, gB + (size_t)r * Kb + c * 16);
    }
    asm volatile("cp.async.commit_group;" ::: "memory");
}

// ---------------- f16-in / f32-acc GEMM (layer 1) -------------------------------
__global__ void __launch_bounds__(256, 2)
gemm_l1(const __half* __restrict__ A, const __half* __restrict__ B,
        float* __restrict__ C, int N, int K)
{
    extern __shared__ char smraw[];
    const uint32_t smbase = smem_u32(smraw);
    const int tid = threadIdx.x, wid = tid >> 5, lid = tid & 31;
    const int bm = blockIdx.y * BM, bn = blockIdx.x * BN;
    const int NC = K / 64;
    const int wm = (wid & 1) * 64, wn = (wid >> 1) * 32;
    const int lr = ((lid >> 3) & 1) * 8 + (lid & 7);
    const int lc = (lid >> 4) * 8;
    const size_t Kb = (size_t)K * 2;

    float acc[4][4][4];
#pragma unroll
    for (int i = 0; i < 4; i++)
#pragma unroll
        for (int j = 0; j < 4; j++)
#pragma unroll
            for (int q = 0; q < 4; q++) acc[i][j][q] = 0.f;

    load_stage((const char*)A, (const char*)B, Kb, bm, bn, smbase, tid, 0, 0);
    load_stage((const char*)A, (const char*)B, Kb, bm, bn, smbase, tid, 1, 1);

    int st = 0;
    for (int kc = 0; kc < NC; ++kc) {
        asm volatile("cp.async.wait_group %0;" :: "n"(STAGES - 2) : "memory");
        __syncthreads();
        const uint32_t aBase = smbase + st * STAGEB;
        const uint32_t bBase = aBase + TILEB;
#pragma unroll
        for (int ks = 0; ks < 4; ++ks) {
            uint32_t a[4][4];
#pragma unroll
            for (int i = 0; i < 4; i++)
                ldsm4(a[i][0], a[i][1], a[i][2], a[i][3],
                      aBase + (uint32_t)(wm + i * 16 + lr) * LDROW
                            + (uint32_t)(ks * 16 + lc) * 2);
            uint32_t b[4][2];
#pragma unroll
            for (int jj = 0; jj < 2; jj++) {
                uint32_t r0, r1, r2, r3;
                ldsm4(r0, r1, r2, r3,
                      bBase + (uint32_t)(wn + jj * 16 + lr) * LDROW
                            + (uint32_t)(ks * 16 + lc) * 2);
                b[jj * 2 + 0][0] = r0; b[jj * 2 + 0][1] = r2;
                b[jj * 2 + 1][0] = r1; b[jj * 2 + 1][1] = r3;
            }
#pragma unroll
            for (int i = 0; i < 4; i++)
#pragma unroll
                for (int j = 0; j < 4; j++)
                    mma_f16_f32(acc[i][j], a[i], b[j]);
        }
        int nk = kc + STAGES - 1;
        if (nk < NC) {
            int nst = st + (STAGES - 1); if (nst >= STAGES) nst -= STAGES;
            load_stage((const char*)A, (const char*)B, Kb, bm, bn, smbase, tid, nst, nk);
        } else
            asm volatile("cp.async.commit_group;" ::: "memory");
        if (++st == STAGES) st = 0;
    }

    const int row0 = lid >> 2, col0 = (lid & 3) * 2;
#pragma unroll
    for (int i = 0; i < 4; i++)
#pragma unroll
        for (int j = 0; j < 4; j++) {
            int m0 = bm + wm + i * 16 + row0;
            int n0 = bn + wn + j * 8 + col0;
            *(float2*)&C[(size_t)m0 * N + n0]       = make_float2(acc[i][j][0], acc[i][j][1]);
            *(float2*)&C[(size_t)(m0 + 8) * N + n0] = make_float2(acc[i][j][2], acc[i][j][3]);
        }
}

// ---------------- f16/f16 GEMM (layers 2/3/4) -----------------------------------
template <int EPI>
__global__ void __launch_bounds__(256, 2)
gemm_f16(const __half* __restrict__ A, const __half* __restrict__ B,
         void* __restrict__ Cv, int N, int K, const float* __restrict__ scale,
         float* __restrict__ ps2, float* __restrict__ pq2)
{
    extern __shared__ char smraw[];
    const uint32_t smbase = smem_u32(smraw);
    const int tid = threadIdx.x, wid = tid >> 5, lid = tid & 31;
    const int bm = blockIdx.y * BM, bn = blockIdx.x * BN;
    const int NC = K / 64;
    const int wm = (wid & 1) * 64, wn = (wid >> 1) * 32;
    const int lr = ((lid >> 3) & 1) * 8 + (lid & 7);
    const int lc = (lid >> 4) * 8;
    const size_t Kb = (size_t)K * 2;

    uint32_t acc[4][4][2];
#pragma unroll
    for (int i = 0; i < 4; i++)
#pragma unroll
        for (int j = 0; j < 4; j++) { acc[i][j][0] = 0u; acc[i][j][1] = 0u; }

    load_stage((const char*)A, (const char*)B, Kb, bm, bn, smbase, tid, 0, 0);
    load_stage((const char*)A, (const char*)B, Kb, bm, bn, smbase, tid, 1, 1);

    int st = 0;
    for (int kc = 0; kc < NC; ++kc) {
        asm volatile("cp.async.wait_group %0;" :: "n"(STAGES - 2) : "memory");
        __syncthreads();
        const uint32_t aBase = smbase + st * STAGEB;
        const uint32_t bBase = aBase + TILEB;
#pragma unroll
        for (int ks = 0; ks < 4; ++ks) {
            uint32_t a[4][4];
#pragma unroll
            for (int i = 0; i < 4; i++)
                ldsm4(a[i][0], a[i][1], a[i][2], a[i][3],
                      aBase + (uint32_t)(wm + i * 16 + lr) * LDROW
                            + (uint32_t)(ks * 16 + lc) * 2);
            uint32_t b[4][2];
#pragma unroll
            for (int jj = 0; jj < 2; jj++) {
                uint32_t r0, r1, r2, r3;
                ldsm4(r0, r1, r2, r3,
                      bBase + (uint32_t)(wn + jj * 16 + lr) * LDROW
                            + (uint32_t)(ks * 16 + lc) * 2);
                b[jj * 2 + 0][0] = r0; b[jj * 2 + 0][1] = r2;
                b[jj * 2 + 1][0] = r1; b[jj * 2 + 1][1] = r3;
            }
#pragma unroll
            for (int i = 0; i < 4; i++)
#pragma unroll
                for (int j = 0; j < 4; j++)
                    mma_f16_f16(acc[i][j], a[i], b[j]);
        }
        int nk = kc + STAGES - 1;
        if (nk < NC) {
            int nst = st + (STAGES - 1); if (nst >= STAGES) nst -= STAGES;
            load_stage((const char*)A, (const char*)B, Kb, bm, bn, smbase, tid, nst, nk);
        } else
            asm volatile("cp.async.commit_group;" ::: "memory");
        if (++st == STAGES) st = 0;
    }

    const int row0 = lid >> 2, col0 = (lid & 3) * 2;
    if (EPI == 0) {
        __half* C = (__half*)Cv;
#pragma unroll
        for (int i = 0; i < 4; i++)
#pragma unroll
            for (int j = 0; j < 4; j++) {
                int m0 = bm + wm + i * 16 + row0;
                int n0 = bn + wn + j * 8 + col0;
                *(uint32_t*)&C[(size_t)m0 * N + n0]       = acc[i][j][0];
                *(uint32_t*)&C[(size_t)(m0 + 8) * N + n0] = acc[i][j][1];
            }
#pragma unroll
        for (int j = 0; j < 4; j++) {
            float s0 = 0.f, s1 = 0.f, q0 = 0.f, q1 = 0.f;
#pragma unroll
            for (int i = 0; i < 4; i++) {
                __half2 v0 = *(__half2*)&acc[i][j][0];
                __half2 v1 = *(__half2*)&acc[i][j][1];
                float a0 = __low2float(v0), b0 = __high2float(v0);
                float a1 = __low2float(v1), b1 = __high2float(v1);
                s0 += a0 + a1;  q0 += a0 * a0 + a1 * a1;
                s1 += b0 + b1;  q1 += b0 * b0 + b1 * b1;
            }
#pragma unroll
            for (int d = 4; d < 32; d <<= 1) {
                s0 += __shfl_xor_sync(0xFFFFFFFFu, s0, d);
                s1 += __shfl_xor_sync(0xFFFFFFFFu, s1, d);
                q0 += __shfl_xor_sync(0xFFFFFFFFu, q0, d);
                q1 += __shfl_xor_sync(0xFFFFFFFFu, q1, d);
            }
            if (lid < 4) {
                int prow = (int)blockIdx.y * 2 + (wid & 1);
                int col  = bn + wn + j * 8 + (lid & 3) * 2;
                *(float2*)&ps2[(size_t)prow * HD + col] = make_float2(s0, s1);
                *(float2*)&pq2[(size_t)prow * HD + col] = make_float2(q0, q1);
            }
        }
    } else {
        float* trans = (float*)smraw;
        __syncthreads();
#pragma unroll
        for (int j = 0; j < 4; j++) {
            int n0 = wn + j * 8 + col0;
            float s0 = scale[bn + n0], s1 = scale[bn + n0 + 1];
#pragma unroll
            for (int i = 0; i < 4; i++) {
                int t0 = wm + i * 16 + row0;
                __half2 v0 = *(__half2*)&acc[i][j][0];
                __half2 v1 = *(__half2*)&acc[i][j][1];
                trans[n0 * 132 + t0]           = __low2float(v0) * s0;
                trans[(n0 + 1) * 132 + t0]     = __high2float(v0) * s1;
                trans[n0 * 132 + t0 + 8]       = __low2float(v1) * s0;
                trans[(n0 + 1) * 132 + t0 + 8] = __high2float(v1) * s1;
            }
        }
        __syncthreads();
        float* y = (float*)Cv;
        const int b0 = bm >> 9;
        const int tb = bm & 511;
        const int n = tid >> 1, half = tid & 1;
        float* yp = y + ((size_t)b0 * FIN + bn + n) * TD + tb + half * 64;
        const float* sp = trans + n * 132 + half * 64;
#pragma unroll
        for (int k = 0; k < 16; k++)
            *(float4*)&yp[k * 4] = *(const float4*)&sp[k * 4];
    }
}

// ---------------- prep kernels -------------------------------------------------
__global__ void transpose_split2(const float* __restrict__ x, __half* __restrict__ xt2) {
    __shared__ float tile[32][33];
    int n = blockIdx.z, t0 = blockIdx.x * 32, f0 = blockIdx.y * 32;
    const float* xp = x + (size_t)n * FIN * TD;
#pragma unroll
    for (int i = 0; i < 4; i++) {
        int f = f0 + threadIdx.y + i * 8;
        tile[threadIdx.y + i * 8][threadIdx.x] = xp[(size_t)f * TD + t0 + threadIdx.x];
    }
    __syncthreads();
#pragma unroll
    for (int i = 0; i < 4; i++) {
        int t = t0 + threadIdx.y + i * 8;
        int f = f0 + threadIdx.x;
        float v = tile[threadIdx.x][threadIdx.y + i * 8];
        __half hi = __float2half_rn(v);
        float r1 = v - __half2float(hi);
        __half lo = __float2half_rn(r1);
        size_t row = (size_t)((size_t)n * TD + t) * 1024;
        xt2[row + f] = hi;
        xt2[row + 512 + f] = lo;
    }
}

__global__ void binw_all(const float* __restrict__ W2, const float* __restrict__ W3,
                         const float* __restrict__ W4, __half* __restrict__ o) {
    const int C2 = HD * HD / 8, C3 = 2 * C2, C4 = C3 + FIN * HD / 8;
    int i = blockIdx.x * 256 + threadIdx.x;
    if (i >= C4) return;
    const float* src;
    size_t off;
    if (i < C2)      { src = W2; off = (size_t)i * 8; }
    else if (i < C3) { src = W3; off = (size_t)(i - C2) * 8; }
    else             { src = W4; off = (size_t)(i - C3) * 8; }
    float4 w0 = *(const float4*)&src[off];
    float4 w1 = *(const float4*)&src[off + 4];
    __half2 p0 = __floats2half2_rn(sgnf(w0.x), sgnf(w0.y));
    __half2 p1 = __floats2half2_rn(sgnf(w0.z), sgnf(w0.w));
    __half2 p2 = __floats2half2_rn(sgnf(w1.x), sgnf(w1.y));
    __half2 p3 = __floats2half2_rn(sgnf(w1.z), sgnf(w1.w));
    uint4 v;
    v.x = *(uint32_t*)&p0; v.y = *(uint32_t*)&p1;
    v.z = *(uint32_t*)&p2; v.w = *(uint32_t*)&p3;
    *(uint4*)&o[(size_t)i * 8] = v;
}
__global__ void binw1(const float* __restrict__ W1, __half* __restrict__ o) {
    int i = blockIdx.x * 256 + threadIdx.x;
    if (i >= HD * FIN / 8) return;
    float4 w0 = *(const float4*)&W1[(size_t)i * 8];
    float4 w1 = *(const float4*)&W1[(size_t)i * 8 + 4];
    int row = (i * 8) >> 9, k = (i * 8) & 511;
    __half2 p0 = __floats2half2_rn(sgnf(w0.x), sgnf(w0.y));
    __half2 p1 = __floats2half2_rn(sgnf(w0.z), sgnf(w0.w));
    __half2 p2 = __floats2half2_rn(sgnf(w1.x), sgnf(w1.y));
    __half2 p3 = __floats2half2_rn(sgnf(w1.z), sgnf(w1.w));
    uint4 v;
    v.x = *(uint32_t*)&p0; v.y = *(uint32_t*)&p1;
    v.z = *(uint32_t*)&p2; v.w = *(uint32_t*)&p3;
    size_t base = (size_t)row * 1024 + k;
    *(uint4*)&o[base] = v;
    *(uint4*)&o[base + 512] = v;
}

// ---------------- BN stats ------------------------------------------------------
__global__ void stats_partial_f32(const float* __restrict__ h,
                                  float* __restrict__ ps, float* __restrict__ pq) {
    int c = threadIdx.x & 31, lane = threadIdx.x >> 5;
    int col = blockIdx.x * 32 + c;
    int r0 = blockIdx.y * (MR / 8);
    float s = 0.f, sq = 0.f;
    for (int i = lane; i < MR / 8; i += 8) {
        float v = h[(size_t)(r0 + i) * HD + col];
        s += v; sq += v * v;
    }
    __shared__ float ss[8][33], sv[8][33];
    ss[lane][c] = s; sv[lane][c] = sq;
    __syncthreads();
    if (lane == 0) {
        float ts = 0.f, tq = 0.f;
#pragma unroll
        for (int l = 0; l < 8; l++) { ts += ss[l][c]; tq += sv[l][c]; }
        ps[blockIdx.y * HD + col] = ts;
        pq[blockIdx.y * HD + col] = tq;
    }
}
__global__ void stats_final(const float* __restrict__ ps, const float* __restrict__ pq,
                            float* __restrict__ mu, float* __restrict__ rs) {
    int col = blockIdx.x * 256 + threadIdx.x;
    if (col >= HD) return;
    float s = 0.f, sq = 0.f;
#pragma unroll
    for (int p = 0; p < 8; p++) { s += ps[p * HD + col]; sq += pq[p * HD + col]; }
    float m = s * (1.f / MR);
    float var = sq * (1.f / MR) - m * m;
    if (var < 0.f) var = 0.f;
    mu[col] = m;
    rs[col] = rsqrtf(var + 1e-5f);
}
__global__ void stats_final128(const float* __restrict__ ps2, const float* __restrict__ pq2,
                               float* __restrict__ mu, float* __restrict__ rs) {
    int col = blockIdx.x * 256 + threadIdx.x;
    if (col >= HD) return;
    float s = 0.f, sq = 0.f;
    for (int p = 0; p < 128; p++) { s += ps2[(size_t)p * HD + col]; sq += pq2[(size_t)p * HD + col]; }
    float m = s * (1.f / MR);
    float var = sq * (1.f / MR) - m * m;
    if (var < 0.f) var = 0.f;
    mu[col] = m;
    rs[col] = rsqrtf(var + 1e-5f);
}

// ---------------- sign activations ----------------------------------------------
__global__ void sign_act_f32(const float* __restrict__ h,
                             const float* __restrict__ mu, const float* __restrict__ rs,
                             const float* __restrict__ g, const float* __restrict__ b,
                             __half* __restrict__ a) {
    size_t i8 = (size_t)blockIdx.x * blockDim.x + threadIdx.x;
    size_t e0 = i8 * 8;
    if (e0 >= (size_t)MR * HD) return;
    int j = (int)(e0 % HD);
    float4 h0 = *(const float4*)&h[e0];
    float4 h1 = *(const float4*)&h[e0 + 4];
    float4 m0 = *(const float4*)&mu[j], m1 = *(const float4*)&mu[j + 4];
    float4 r0 = *(const float4*)&rs[j], r1 = *(const float4*)&rs[j + 4];
    float4 g0 = *(const float4*)&g[j],  g1 = *(const float4*)&g[j + 4];
    float4 b0 = *(const float4*)&b[j],  b1 = *(const float4*)&b[j + 4];
    __half2 p0 = __floats2half2_rn(sgnf(g0.x * (h0.x - m0.x) * r0.x + b0.x),
                                   sgnf(g0.y * (h0.y - m0.y) * r0.y + b0.y));
    __half2 p1 = __floats2half2_rn(sgnf(g0.z * (h0.z - m0.z) * r0.z + b0.z),
                                   sgnf(g0.w * (h0.w - m0.w) * r0.w + b0.w));
    __half2 p2 = __floats2half2_rn(sgnf(g1.x * (h1.x - m1.x) * r1.x + b1.x),
                                   sgnf(g1.y * (h1.y - m1.y) * r1.y + b1.y));
    __half2 p3 = __floats2half2_rn(sgnf(g1.z * (h1.z - m1.z) * r1.z + b1.z),
                                   sgnf(g1.w * (h1.w - m1.w) * r1.w + b1.w));
    uint4 v;
    v.x = *(uint32_t*)&p0; v.y = *(uint32_t*)&p1;
    v.z = *(uint32_t*)&p2; v.w = *(uint32_t*)&p3;
    *(uint4*)&a[e0] = v;
}
__global__ void sign_act_f16(const __half* __restrict__ h,
                             const float* __restrict__ mu, const float* __restrict__ rs,
                             const float* __restrict__ g, const float* __restrict__ b,
                             __half* __restrict__ a) {
    size_t i8 = (size_t)blockIdx.x * blockDim.x + threadIdx.x;
    size_t e0 = i8 * 8;
    if (e0 >= (size_t)MR * HD) return;
    int j = (int)(e0 % HD);
    uint4 hv = *(const uint4*)&h[e0];
    const __half2* hp = (const __half2*)&hv;
    float4 m0 = *(const float4*)&mu[j], m1 = *(const float4*)&mu[j + 4];
    float4 r0 = *(const float4*)&rs[j], r1 = *(const float4*)&rs[j + 4];
    float4 g0 = *(const float4*)&g[j],  g1 = *(const float4*)&g[j + 4];
    float4 b0 = *(const float4*)&b[j],  b1 = *(const float4*)&b[j + 4];
    __half2 p0 = __floats2half2_rn(
        sgnf(g0.x * (__low2float(hp[0]) - m0.x) * r0.x + b0.x),
        sgnf(g0.y * (__high2float(hp[0]) - m0.y) * r0.y + b0.y));
    __half2 p1 = __floats2half2_rn(
        sgnf(g0.z * (__low2float(hp[1]) - m0.z) * r0.z + b0.z),
        sgnf(g0.w * (__high2float(hp[1]) - m0.w) * r0.w + b0.w));
    __half2 p2 = __floats2half2_rn(
        sgnf(g1.x * (__low2float(hp[2]) - m1.x) * r1.x + b1.x),
        sgnf(g1.y * (__high2float(hp[2]) - m1.y) * r1.y + b1.y));
    __half2 p3 = __floats2half2_rn(
        sgnf(g1.z * (__low2float(hp[3]) - m1.z) * r1.z + b1.z),
        sgnf(g1.w * (__high2float(hp[3]) - m1.w) * r1.w + b1.w));
    uint4 v;
    v.x = *(uint32_t*)&p0; v.y = *(uint32_t*)&p1;
    v.z = *(uint32_t*)&p2; v.w = *(uint32_t*)&p3;
    *(uint4*)&a[e0] = v;
}

// ---------------- host orchestration --------------------------------------------
extern "C" void kernel_launch(void* const* d_in, const int* in_sizes, int n_in,
                              void* d_out, int out_size) {
    const float* x     = (const float*)d_in[0];
    const float* W1    = (const float*)d_in[2];
    const float* g1    = (const float*)d_in[3];
    const float* b1    = (const float*)d_in[4];
    const float* W2    = (const float*)d_in[5];
    const float* g2    = (const float*)d_in[6];
    const float* b2    = (const float*)d_in[7];
    const float* W3    = (const float*)d_in[8];
    const float* g3    = (const float*)d_in[9];
    const float* b3    = (const float*)d_in[10];
    const float* W4    = (const float*)d_in[11];
    const float* scale = (const float*)d_in[12];
    float* y = (float*)d_out;

    __half *xt2, *w1b, *wb, *a;
    float *h, *mu, *rs, *ps, *pq, *ps2, *pq2;
    cudaGetSymbolAddress((void**)&xt2, g_xt2);
    cudaGetSymbolAddress((void**)&w1b, g_w1b);
    cudaGetSymbolAddress((void**)&wb,  g_wb);
    cudaGetSymbolAddress((void**)&h,   g_h);
    cudaGetSymbolAddress((void**)&a,   g_a);
    cudaGetSymbolAddress((void**)&mu,  g_mu);
    cudaGetSymbolAddress((void**)&rs,  g_rs);
    cudaGetSymbolAddress((void**)&ps,  g_ps);
    cudaGetSymbolAddress((void**)&pq,  g_pq);
    cudaGetSymbolAddress((void**)&ps2, g_ps2);
    cudaGetSymbolAddress((void**)&pq2, g_pq2);
    __half* h16 = (__half*)h;
    __half* w2b = wb;
    __half* w3b = wb + (size_t)HD * HD;
    __half* w4b = wb + (size_t)2 * HD * HD;

    cudaFuncSetAttribute(gemm_l1,     cudaFuncAttributeMaxDynamicSharedMemorySize, SMEM_DYN);
    cudaFuncSetAttribute(gemm_f16<0>, cudaFuncAttributeMaxDynamicSharedMemorySize, SMEM_DYN);
    cudaFuncSetAttribute(gemm_f16<1>, cudaFuncAttributeMaxDynamicSharedMemorySize, SMEM_DYN);

    // prep
    transpose_split2<<<dim3(TD / 32, FIN / 32, NB), dim3(32, 8)>>>(x, xt2);
    binw1<<<(HD * FIN / 8 + 255) / 256, 256>>>(W1, w1b);
    {
        int chunks = (2 * HD * HD + FIN * HD) / 8;
        binw_all<<<(chunks + 255) / 256, 256>>>(W2, W3, W4, wb);
    }

    dim3 blk(256);
    dim3 gridStats(HD / 32, 8);
    dim3 gridSign((unsigned)(((size_t)MR * HD / 8 + 255) / 256));
    dim3 gGemm(HD / BN, MR / BM);   // (16, 64)
    dim3 gGemm4(FIN / BN, MR / BM); // (4, 64)

    // layer 1 (f16 2-way split, f32 accum, K=1024)
    gemm_l1<<<gGemm, blk, SMEM_DYN>>>(xt2, w1b, h, HD, 1024);
    stats_partial_f32<<<gridStats, blk>>>(h, ps, pq);
    stats_final<<<dim3(HD / 256), blk>>>(ps, pq, mu, rs);
    sign_act_f32<<<gridSign, blk>>>(h, mu, rs, g1, b1, a);

    // layer 2
    gemm_f16<0><<<gGemm, blk, SMEM_DYN>>>(a, w2b, h16, HD, HD, nullptr, ps2, pq2);
    stats_final128<<<dim3(HD / 256), blk>>>(ps2, pq2, mu, rs);
    sign_act_f16<<<gridSign, blk>>>(h16, mu, rs, g2, b2, a);

    // layer 3
    gemm_f16<0><<<gGemm, blk, SMEM_DYN>>>(a, w3b, h16, HD, HD, nullptr, ps2, pq2);
    stats_final128<<<dim3(HD / 256), blk>>>(ps2, pq2, mu, rs);
    sign_act_f16<<<gridSign, blk>>>(h16, mu, rs, g3, b3, a);

    // layer 4
    gemm_f16<1><<<gGemm4, blk, SMEM_DYN>>>(a, w4b, y, FIN, HD, scale, nullptr, nullptr);
}